// round 15
// baseline (speedup 1.0000x reference)
#include <cuda_runtime.h>
#include <cuda_bf16.h>
#include <cstdint>
#include <cstddef>

using bf16 = __nv_bfloat16;

#define Tseq 4096
#define CDIM 1024
#define NH   16
#define HD   64
#define WSZ  (CDIM * CDIM)
#define NEG_INF (-1e30f)

// ---------------- scratch (device globals: no allocation allowed) ----------
__device__ float g_Q[Tseq * CDIM];
__device__ float g_K[Tseq * CDIM];
__device__ float g_V[Tseq * CDIM];
__device__ float g_FO[Tseq * CDIM];
__device__ float g_fm[Tseq * NH];
__device__ float g_fl[Tseq * NH];
// packed tile-blocked, pre-swizzled tf32 operands (GEMM):
// block (rtile, ks) at ((rtile*32 + ks) << 14); inside: row rr x chunk s:
// rr*128 + ((s ^ (rr&7)) << 4)
__device__ uint32_t g_xt[Tseq * CDIM];
__device__ uint32_t g_ot[Tseq * CDIM];
__device__ uint32_t g_wt[4 * WSZ];
// packed per-(head, kblock) 8KB pre-swizzled bf16 K/V tiles (attention)
__device__ bf16  g_kh[Tseq * CDIM];
__device__ bf16  g_kl[Tseq * CDIM];
__device__ bf16  g_vh[Tseq * CDIM];
__device__ bf16  g_vl[Tseq * CDIM];

// ---------------- helpers ----------------
__device__ __forceinline__ uint32_t smem_u32(const void* p) {
    uint32_t a;
    asm("{ .reg .u64 t; cvta.to.shared.u64 t, %1; cvt.u32.u64 %0, t; }" : "=r"(a) : "l"(p));
    return a;
}

#define LDSM_X4(r0, r1, r2, r3, addr) \
    asm volatile("ldmatrix.sync.aligned.m8n8.x4.shared.b16 {%0,%1,%2,%3}, [%4];" \
                 : "=r"(r0), "=r"(r1), "=r"(r2), "=r"(r3) : "r"(addr))

#define LDSM_X4_T(r0, r1, r2, r3, addr) \
    asm volatile("ldmatrix.sync.aligned.m8n8.x4.trans.shared.b16 {%0,%1,%2,%3}, [%4];" \
                 : "=r"(r0), "=r"(r1), "=r"(r2), "=r"(r3) : "r"(addr))

#define MMA_BF16(c, a, b0, b1) \
    asm volatile("mma.sync.aligned.m16n8k16.row.col.f32.bf16.bf16.f32 " \
                 "{%0,%1,%2,%3}, {%4,%5,%6,%7}, {%8,%9}, {%0,%1,%2,%3};" \
                 : "+f"((c)[0]), "+f"((c)[1]), "+f"((c)[2]), "+f"((c)[3]) \
                 : "r"((a)[0]), "r"((a)[1]), "r"((a)[2]), "r"((a)[3]), "r"(b0), "r"(b1))

#define MMA_TF32(c, a, b0, b1) \
    asm volatile("mma.sync.aligned.m16n8k8.row.col.f32.tf32.tf32.f32 " \
                 "{%0,%1,%2,%3}, {%4,%5,%6,%7}, {%8,%9}, {%0,%1,%2,%3};" \
                 : "+f"((c)[0]), "+f"((c)[1]), "+f"((c)[2]), "+f"((c)[3]) \
                 : "r"((a)[0]), "r"((a)[1]), "r"((a)[2]), "r"((a)[3]), "r"(b0), "r"(b1))

#define PACK_BF16X2(d, hi, lo) \
    asm("cvt.rn.bf16x2.f32 %0, %1, %2;" : "=r"(d) : "f"(hi), "f"(lo))

#define CVT_TF32(d, f) \
    asm("cvt.rna.tf32.f32 %0, %1;" : "=r"(d) : "f"(f))

#define MBAR_INIT(a, c) asm volatile("mbarrier.init.shared.b64 [%0], %1;" :: "r"((uint32_t)(a)), "r"((uint32_t)(c)) : "memory")
#define MBAR_EXPECT(a, bytes) \
    asm volatile("mbarrier.arrive.expect_tx.shared.b64 _, [%0], %1;" :: "r"((uint32_t)(a)), "r"((uint32_t)(bytes)) : "memory")
#define MBAR_WAIT(a, ph) do {                                                            \
    uint32_t _m = (uint32_t)(a), _p = (uint32_t)(ph), _d;                                \
    asm volatile("{\n\t.reg .pred p;\n\tmbarrier.try_wait.parity.acquire.cta.shared::cta.b64 p, [%1], %2;\n\tselp.b32 %0, 1, 0, p;\n\t}" \
                 : "=r"(_d) : "r"(_m), "r"(_p) : "memory");                              \
    if (!_d) {                                                                           \
        asm volatile("{\n\t.reg .pred P1;\n\tWL_%=:\n\tmbarrier.try_wait.parity.acquire.cta.shared::cta.b64 P1, [%0], %1, 0x989680;\n\t@P1 bra.uni WD_%=;\n\tbra.uni WL_%=;\n\tWD_%=:\n\t}" \
                     :: "r"(_m), "r"(_p) : "memory");                                    \
    }                                                                                    \
} while (0)

#define CP_BULK(dst, src, n, mbar) \
    asm volatile("cp.async.bulk.shared::cluster.global.mbarrier::complete_tx::bytes [%0], [%1], %2, [%3];" \
                 :: "r"((uint32_t)(dst)), "l"(src), "r"((uint32_t)(n)), "r"((uint32_t)(mbar)) : "memory")

#define FENCE_ASYNC()  asm volatile("fence.proxy.async.shared::cta;" ::: "memory")

__device__ __forceinline__ void split_pack2(float a, float b, uint32_t& h2, uint32_t& l2)
{
    PACK_BF16X2(h2, b, a);
    float ar = a - __bfloat162float(__float2bfloat16(a));
    float br = b - __bfloat162float(__float2bfloat16(b));
    PACK_BF16X2(l2, br, ar);
}

// ---------------- fp32 -> packed pre-swizzled tf32 (x + 4 weights) ---------
__global__ __launch_bounds__(256) void pack_tf32_all(const float* __restrict__ x,
                                                     const float* __restrict__ Wq,
                                                     const float* __restrict__ Wk,
                                                     const float* __restrict__ Wv,
                                                     const float* __restrict__ Wo)
{
    int blk = blockIdx.x;
    const float* src;
    uint32_t* dst;
    int i;
    if (blk < 4096) {
        src = x; dst = g_xt;
        i = blk * 256 + threadIdx.x;
    } else {
        int wsel = (blk - 4096) >> 10;
        int wblk = (blk - 4096) & 1023;
        src = (wsel == 0) ? Wq : (wsel == 1) ? Wk : (wsel == 2) ? Wv : Wo;
        dst = g_wt + (size_t)wsel * WSZ;
        i = wblk * 256 + threadIdx.x;
    }
    int r = i >> 8;
    int c16 = i & 255;
    const float* sp = src + (size_t)r * CDIM + c16 * 4;
    float4 v = *(const float4*)sp;
    uint32_t t[4];
    CVT_TF32(t[0], v.x); CVT_TF32(t[1], v.y);
    CVT_TF32(t[2], v.z); CVT_TF32(t[3], v.w);
    int rt = r >> 7, rr = r & 127;
    int ks = c16 >> 3, s = c16 & 7;
    size_t boff = ((size_t)(rt * 32 + ks) << 14) + rr * 128 + ((s ^ (rr & 7)) << 4);
    *(uint4*)((char*)dst + boff) = *(uint4*)t;
}

// ---------------- K/V fp32 -> packed per-(h,kb) 8KB bf16 hi/lo tiles -------
__global__ __launch_bounds__(128) void kv_convert()
{
    int b = blockIdx.x;
    int h = b >> 6, kb = b & 63;
#pragma unroll
    for (int it = 0; it < 4; it++) {
        int id = threadIdx.x + it * 128;
        int r = id >> 3, s = id & 7;
        size_t goff = ((size_t)b << 13) + r * 128 + ((s ^ (r & 7)) << 4);
        const float* kp = g_K + (size_t)(kb * 64 + r) * CDIM + h * HD + s * 8;
        const float* vp = g_V + (size_t)(kb * 64 + r) * CDIM + h * HD + s * 8;
        float4 k0 = *(const float4*)kp, k1 = *(const float4*)(kp + 4);
        float4 w0 = *(const float4*)vp, w1 = *(const float4*)(vp + 4);
        float ka[8] = {k0.x, k0.y, k0.z, k0.w, k1.x, k1.y, k1.z, k1.w};
        float va[8] = {w0.x, w0.y, w0.z, w0.w, w1.x, w1.y, w1.z, w1.w};
        bf16 khh[8], kll[8], vhh[8], vll[8];
#pragma unroll
        for (int k = 0; k < 8; k++) {
            khh[k] = __float2bfloat16(ka[k]);
            kll[k] = __float2bfloat16(ka[k] - __bfloat162float(khh[k]));
            vhh[k] = __float2bfloat16(va[k]);
            vll[k] = __float2bfloat16(va[k] - __bfloat162float(vhh[k]));
        }
        *(uint4*)((char*)g_kh + goff) = *(uint4*)khh;
        *(uint4*)((char*)g_kl + goff) = *(uint4*)kll;
        *(uint4*)((char*)g_vh + goff) = *(uint4*)vhh;
        *(uint4*)((char*)g_vl + goff) = *(uint4*)vll;
    }
}

// ---------------- tf32 single-pass GEMM: C[4096,1024] = A @ B^T ------------
// CTA tile 128x128, BK=32 floats. 256 threads = 8 warps (4M x 2N).
// Fragments via ldmatrix.x4 (b16 word distribution == tf32 fragment layout).
constexpr int BLK_B = 16384;
constexpr int STG_B = 2 * BLK_B;
constexpr int NSTAGE = 5;
constexpr int SMEM_GEMM = NSTAGE * STG_B + 64;

__device__ __forceinline__ void issue_stage(const uint32_t* __restrict__ A,
                                            const uint32_t* __restrict__ B,
                                            int bmT, int bnT, int kt,
                                            uint32_t bufu, uint32_t mbar, int tid)
{
    if (tid == 0) MBAR_EXPECT(mbar, STG_B);
    if (tid < 2) {
        const uint32_t* base = tid ? B : A;
        int rT = tid ? bnT : bmT;
        size_t bl = ((size_t)(rT * 32 + kt)) << 14;
        CP_BULK(bufu + tid * BLK_B, (const char*)base + bl, BLK_B, mbar);
    }
}

__device__ __forceinline__ void gemm_body(const uint32_t* __restrict__ A,
                                          const uint32_t* __restrict__ B,
                                          float* __restrict__ C)
{
    extern __shared__ __align__(128) unsigned char dynsmem[];
    uint32_t sb = smem_u32(dynsmem);
    const uint32_t mb = sb + NSTAGE * STG_B;
    const int tid = threadIdx.x;
    const int lane = tid & 31;
    const int wid = tid >> 5;
    const int bmT = blockIdx.y;
    const int bnT = blockIdx.x;
    const int m0 = (wid & 3) * 32;
    const int n0 = (wid >> 2) * 64;
    const int la = lane & 3;
    const int g4 = lane >> 2;
    const int mtx = lane >> 3;        // ldmatrix matrix index 0..3
    const int rw  = lane & 7;         // row within matrix

    if (tid == 0) {
#pragma unroll
        for (int s = 0; s < NSTAGE; s++) MBAR_INIT(mb + 8 * s, 1);
    }
    FENCE_ASYNC();
    __syncthreads();

    float acc[2][8][4];
#pragma unroll
    for (int mt = 0; mt < 2; mt++)
#pragma unroll
        for (int nt = 0; nt < 8; nt++)
#pragma unroll
            for (int c = 0; c < 4; c++) acc[mt][nt][c] = 0.f;

#pragma unroll
    for (int kt = 0; kt < NSTAGE; kt++)
        issue_stage(A, B, bmT, bnT, kt, sb + kt * STG_B, mb + 8 * kt, tid);

    int ph[NSTAGE] = {0, 0, 0, 0, 0};
    int b = 0;

#pragma unroll 1
    for (int kt = 0; kt < 32; ++kt) {
        MBAR_WAIT(mb + 8 * b, ph[b]);
        ph[b] ^= 1;
        const uint32_t cbA = sb + b * STG_B;
        const uint32_t cbB = cbA + BLK_B;

#pragma unroll
        for (int ks8 = 0; ks8 < 4; ++ks8) {
            const int ch0 = 2 * ks8;
            // A fragments: x4 matrices = {rows 0-7 ch0, rows 8-15 ch0,
            //                             rows 0-7 ch0+1, rows 8-15 ch0+1}
            uint32_t af[2][4];
#pragma unroll
            for (int mt = 0; mt < 2; mt++) {
                int row = m0 + mt * 16 + ((mtx & 1) ? 8 : 0) + rw;
                int ch = (mtx & 2) ? (ch0 + 1) : ch0;
                uint32_t addr = cbA + row * 128 + ((ch ^ (row & 7)) << 4);
                LDSM_X4(af[mt][0], af[mt][1], af[mt][2], af[mt][3], addr);
            }
            // B fragments: x4 covers 2 n-tiles = {np even ch0, np even ch0+1,
            //                                     np odd ch0, np odd ch0+1}
#pragma unroll
            for (int np2 = 0; np2 < 4; np2++) {
                int nr = n0 + np2 * 16 + ((mtx >> 1) ? 8 : 0) + rw;
                int ch = (mtx & 1) ? (ch0 + 1) : ch0;
                uint32_t addr = cbB + nr * 128 + ((ch ^ (nr & 7)) << 4);
                uint32_t bf[4];
                LDSM_X4(bf[0], bf[1], bf[2], bf[3], addr);
                MMA_TF32(acc[0][2 * np2],     af[0], bf[0], bf[1]);
                MMA_TF32(acc[1][2 * np2],     af[1], bf[0], bf[1]);
                MMA_TF32(acc[0][2 * np2 + 1], af[0], bf[2], bf[3]);
                MMA_TF32(acc[1][2 * np2 + 1], af[1], bf[2], bf[3]);
            }
        }
        __syncthreads();
        if (kt + NSTAGE < 32)
            issue_stage(A, B, bmT, bnT, kt + NSTAGE, sb + b * STG_B, mb + 8 * b, tid);
        b = (b + 1 == NSTAGE) ? 0 : b + 1;
    }

    // epilogue
#pragma unroll
    for (int mt = 0; mt < 2; mt++) {
        int row = bmT * 128 + m0 + mt * 16 + g4;
#pragma unroll
        for (int nt = 0; nt < 8; nt++) {
            int col = bnT * 128 + n0 + nt * 8 + 2 * la;
            float* p = C + (size_t)row * CDIM + col;
            *(float2*)p = make_float2(acc[mt][nt][0], acc[mt][nt][1]);
            *(float2*)(p + 8 * CDIM) = make_float2(acc[mt][nt][2], acc[mt][nt][3]);
        }
    }
}

__global__ __launch_bounds__(256) void qkv_gemm()
{
    int z = blockIdx.z;
    float* C = (z == 0) ? g_Q : (z == 1) ? g_K : g_V;
    gemm_body(g_xt, g_wt + (size_t)z * WSZ, C);
}

__global__ __launch_bounds__(256) void oproj_gemm(float* __restrict__ out)
{
    gemm_body(g_ot, g_wt + 3 * (size_t)WSZ, out);
}

// ---------------- attention helpers (far kernel) ----------------
__device__ __forceinline__ void stage_hl_s(const float* __restrict__ g, int base,
                                           int stride, int h, bf16* sh, bf16* sl,
                                           int tid)
{
#pragma unroll
    for (int s = 0; s < 4; s++) {
        int sid = tid + s * 128;
        int r = sid >> 3, sl8 = sid & 7;
        const float* src = g + (size_t)(base + r * stride) * CDIM + h * HD + sl8 * 8;
        float4 v0 = *(const float4*)src;
        float4 v1 = *(const float4*)(src + 4);
        float a[8] = {v0.x, v0.y, v0.z, v0.w, v1.x, v1.y, v1.z, v1.w};
        bf16 hi[8], lo[8];
#pragma unroll
        for (int k = 0; k < 8; k++) {
            hi[k] = __float2bfloat16(a[k]);
            lo[k] = __float2bfloat16(a[k] - __bfloat162float(hi[k]));
        }
        uint32_t off = r * 128 + ((sl8 ^ (r & 7)) * 16);
        *(uint4*)((char*)sh + off) = *(uint4*)hi;
        *(uint4*)((char*)sl + off) = *(uint4*)lo;
    }
}

// ---------------- far strided attention over residue classes ----------------
__global__ __launch_bounds__(128) void far_attn_kernel()
{
    __shared__ __align__(128) bf16 sKH[4096];
    __shared__ __align__(128) bf16 sKL[4096];
    __shared__ __align__(128) bf16 sVH[4096];
    __shared__ __align__(128) bf16 sVL[4096];

    const int c  = blockIdx.x;
    const int h  = blockIdx.y;
    const int tid = threadIdx.x;
    const int lane = tid & 31;
    const int w = tid >> 5;
    const int row16 = lane >> 2;
    const int quad = lane & 3;
    const int mrow = w * 16 + row16;
    const int q0row = c + 64 * mrow;
    const int q1row = q0row + 512;

    float q0[16], q1[16];
    {
        const float* qp0 = g_Q + (size_t)q0row * CDIM + h * HD;
        const float* qp1 = g_Q + (size_t)q1row * CDIM + h * HD;
#pragma unroll
        for (int j = 0; j < 8; j++) {
            float2 a = *(const float2*)(qp0 + 8 * j + 2 * quad);
            float2 b = *(const float2*)(qp1 + 8 * j + 2 * quad);
            q0[2 * j] = a.x * 0.125f; q0[2 * j + 1] = a.y * 0.125f;
            q1[2 * j] = b.x * 0.125f; q1[2 * j + 1] = b.y * 0.125f;
        }
    }
    uint32_t qh[4][4], ql[4][4];
#pragma unroll
    for (int kk = 0; kk < 4; kk++) {
        split_pack2(q0[4 * kk],     q0[4 * kk + 1], qh[kk][0], ql[kk][0]);
        split_pack2(q1[4 * kk],     q1[4 * kk + 1], qh[kk][1], ql[kk][1]);
        split_pack2(q0[4 * kk + 2], q0[4 * kk + 3], qh[kk][2], ql[kk][2]);
        split_pack2(q1[4 * kk + 2], q1[4 * kk + 3], qh[kk][3], ql[kk][3]);
    }

    stage_hl_s(g_K, c, 64, h, sKH, sKL, tid);
    stage_hl_s(g_V, c, 64, h, sVH, sVL, tid);
    __syncthreads();

    const uint32_t uKH = smem_u32(sKH), uKL = smem_u32(sKL);
    const uint32_t uVH = smem_u32(sVH), uVL = smem_u32(sVL);
    const int bmat = lane >> 3;
    const int brow_in = ((bmat & 2) ? 8 : 0) + (lane & 7);
    const int bslot_in = bmat & 1;
    const int v_row_in = ((lane >> 3) & 1) * 8 + (lane & 7);
    const int v_sel = lane >> 4;

    float sacc[8][4];
#pragma unroll
    for (int t = 0; t < 8; t++)
#pragma unroll
        for (int cc = 0; cc < 4; cc++) sacc[t][cc] = 0.f;
#pragma unroll
    for (int kk = 0; kk < 4; kk++) {
#pragma unroll
        for (int np = 0; np < 4; np++) {
            int r = np * 16 + brow_in;
            uint32_t off = r * 128 + (((2 * kk + bslot_in) ^ (r & 7)) * 16);
            uint32_t b[4];
            LDSM_X4(b[0], b[1], b[2], b[3], uKH + off);
            MMA_BF16(sacc[2 * np],     qh[kk], b[0], b[1]);
            MMA_BF16(sacc[2 * np + 1], qh[kk], b[2], b[3]);
            MMA_BF16(sacc[2 * np],     ql[kk], b[0], b[1]);
            MMA_BF16(sacc[2 * np + 1], ql[kk], b[2], b[3]);
            LDSM_X4(b[0], b[1], b[2], b[3], uKL + off);
            MMA_BF16(sacc[2 * np],     qh[kk], b[0], b[1]);
            MMA_BF16(sacc[2 * np + 1], qh[kk], b[2], b[3]);
        }
    }

    float rmax0 = NEG_INF, rmax1 = NEG_INF;
#pragma unroll
    for (int t = 0; t < 8; t++) {
#pragma unroll
        for (int cc = 0; cc < 4; cc++) {
            int m = mrow + ((cc >> 1) ? 8 : 0);
            int j = t * 8 + 2 * quad + (cc & 1);
            float s = (m - j >= 5) ? sacc[t][cc] : NEG_INF;
            sacc[t][cc] = s;
            if (cc < 2) rmax0 = fmaxf(rmax0, s);
            else        rmax1 = fmaxf(rmax1, s);
        }
    }
    rmax0 = fmaxf(rmax0, __shfl_xor_sync(0xFFFFFFFFu, rmax0, 1));
    rmax0 = fmaxf(rmax0, __shfl_xor_sync(0xFFFFFFFFu, rmax0, 2));
    rmax1 = fmaxf(rmax1, __shfl_xor_sync(0xFFFFFFFFu, rmax1, 1));
    rmax1 = fmaxf(rmax1, __shfl_xor_sync(0xFFFFFFFFu, rmax1, 2));
    float base0 = (rmax0 > -1e29f) ? 1.f : 0.f;
    float base1 = (rmax1 > -1e29f) ? 1.f : 0.f;
    float sum0 = 0.f, sum1 = 0.f;
#pragma unroll
    for (int t = 0; t < 8; t++) {
#pragma unroll
        for (int cc = 0; cc < 4; cc++) {
            float bb = (cc < 2) ? base0 : base1;
            float mm = (cc < 2) ? rmax0 : rmax1;
            float p = bb * __expf(sacc[t][cc] - mm);
            sacc[t][cc] = p;
            if (cc < 2) sum0 += p; else sum1 += p;
        }
    }
    sum0 += __shfl_xor_sync(0xFFFFFFFFu, sum0, 1);
    sum0 += __shfl_xor_sync(0xFFFFFFFFu, sum0, 2);
    sum1 += __shfl_xor_sync(0xFFFFFFFFu, sum1, 1);
    sum1 += __shfl_xor_sync(0xFFFFFFFFu, sum1, 2);

    float oacc[8][4];
#pragma unroll
    for (int t = 0; t < 8; t++)
#pragma unroll
        for (int cc = 0; cc < 4; cc++) oacc[t][cc] = 0.f;
#pragma unroll
    for (int j = 0; j < 4; j++) {
        uint32_t pfh[4], pfl[4];
        split_pack2(sacc[2 * j][0],     sacc[2 * j][1],     pfh[0], pfl[0]);
        split_pack2(sacc[2 * j][2],     sacc[2 * j][3],     pfh[1], pfl[1]);
        split_pack2(sacc[2 * j + 1][0], sacc[2 * j + 1][1], pfh[2], pfl[2]);
        split_pack2(sacc[2 * j + 1][2], sacc[2 * j + 1][3], pfh[3], pfl[3]);
#pragma unroll
        for (int np = 0; np < 4; np++) {
            int r = j * 16 + v_row_in;
            uint32_t off = r * 128 + (((2 * np + v_sel) ^ (r & 7)) * 16);
            uint32_t vh[4], vl[4];
            LDSM_X4_T(vh[0], vh[1], vh[2], vh[3], uVH + off);
            LDSM_X4_T(vl[0], vl[1], vl[2], vl[3], uVL + off);
            MMA_BF16(oacc[2 * np],     pfh, vh[0], vh[1]);
            MMA_BF16(oacc[2 * np],     pfl, vh[0], vh[1]);
            MMA_BF16(oacc[2 * np],     pfh, vl[0], vl[1]);
            MMA_BF16(oacc[2 * np + 1], pfh, vh[2], vh[3]);
            MMA_BF16(oacc[2 * np + 1], pfl, vh[2], vh[3]);
            MMA_BF16(oacc[2 * np + 1], pfh, vl[2], vl[3]);
        }
    }

#pragma unroll
    for (int t = 0; t < 8; t++) {
        int col = h * HD + t * 8 + 2 * quad;
        *(float2*)(g_FO + (size_t)q0row * CDIM + col) = make_float2(oacc[t][0], oacc[t][1]);
        *(float2*)(g_FO + (size_t)q1row * CDIM + col) = make_float2(oacc[t][2], oacc[t][3]);
    }
    if (quad == 0) {
        g_fm[q0row * NH + h] = rmax0;
        g_fl[q0row * NH + h] = sum0;
        g_fm[q1row * NH + h] = rmax1;
        g_fl[q1row * NH + h] = sum1;
    }
}

// packed tf32 write address for O
__device__ __forceinline__ size_t packed_off32(int row, int col)
{
    int rt = row >> 7, rr = row & 127;
    int ks = col >> 5;
    int c32 = col & 31;
    int s = c32 >> 2, idx = c32 & 3;
    return ((size_t)(rt * 32 + ks) << 14) + rr * 128 + ((s ^ (rr & 7)) << 4) + idx * 4;
}

// ---------------- window attention: bulk-staged pipeline -------------------
constexpr int ASTAGE_B = 32768;
constexpr int SMEM_ATTN = 2 * ASTAGE_B + 64;

__device__ __forceinline__ void issue_attn_stage(int h, int kb, uint32_t bufu,
                                                 uint32_t mbar, int tid)
{
    if (tid == 0) MBAR_EXPECT(mbar, ASTAGE_B);
    if (tid < 4) {
        const bf16* base = (tid == 0) ? g_kh : (tid == 1) ? g_kl : (tid == 2) ? g_vh : g_vl;
        size_t bl = ((size_t)(h * 64 + kb)) << 13;
        CP_BULK(bufu + tid * 8192, (const char*)base + bl, 8192, mbar);
    }
}

__global__ __launch_bounds__(128) void attn_kernel()
{
    extern __shared__ __align__(128) unsigned char dynsmem[];
    uint32_t sb = smem_u32(dynsmem);
    const uint32_t mb = sb + 2 * ASTAGE_B;

    const int qb = blockIdx.x;
    const int h  = blockIdx.y;
    const int tid = threadIdx.x;
    const int lane = tid & 31;
    const int w = tid >> 5;
    const int row16 = lane >> 2;
    const int quad = lane & 3;
    const int r0g = qb * 64 + w * 16 + row16;

    if (tid == 0) { MBAR_INIT(mb, 1); MBAR_INIT(mb + 8, 1); }
    FENCE_ASYNC();
    __syncthreads();

    const int wstart = (qb >= 4) ? qb - 4 : 0;
    const int nblk = qb - wstart + 1;

    issue_attn_stage(h, wstart, sb, mb, tid);
    if (nblk > 1) issue_attn_stage(h, wstart + 1, sb + ASTAGE_B, mb + 8, tid);

    float q0[16], q1[16];
    {
        const float* qp0 = g_Q + (size_t)r0g * CDIM + h * HD;
#pragma unroll
        for (int j = 0; j < 8; j++) {
            float2 a = *(const float2*)(qp0 + 8 * j + 2 * quad);
            float2 b = *(const float2*)(qp0 + 8 * CDIM + 8 * j + 2 * quad);
            q0[2 * j] = a.x * 0.125f; q0[2 * j + 1] = a.y * 0.125f;
            q1[2 * j] = b.x * 0.125f; q1[2 * j + 1] = b.y * 0.125f;
        }
    }
    uint32_t qh[4][4], ql[4][4];
#pragma unroll
    for (int kk = 0; kk < 4; kk++) {
        split_pack2(q0[4 * kk],     q0[4 * kk + 1], qh[kk][0], ql[kk][0]);
        split_pack2(q1[4 * kk],     q1[4 * kk + 1], qh[kk][1], ql[kk][1]);
        split_pack2(q0[4 * kk + 2], q0[4 * kk + 3], qh[kk][2], ql[kk][2]);
        split_pack2(q1[4 * kk + 2], q1[4 * kk + 3], qh[kk][3], ql[kk][3]);
    }

    float oacc[8][4];
#pragma unroll
    for (int t = 0; t < 8; t++)
#pragma unroll
        for (int cc = 0; cc < 4; cc++) oacc[t][cc] = 0.f;
    float m0 = NEG_INF, m1 = NEG_INF, l0 = 0.f, l1 = 0.f;

    const int bmat = lane >> 3;
    const int brow_in = ((bmat & 2) ? 8 : 0) + (lane & 7);
    const int bslot_in = bmat & 1;
    const int v_row_in = ((lane >> 3) & 1) * 8 + (lane & 7);
    const int v_sel = lane >> 4;

    int ph[2] = {0, 0};

#pragma unroll 1
    for (int i = 0; i < nblk; ++i) {
        const int kb = wstart + i;
        const int b = i & 1;
        MBAR_WAIT(mb + 8 * b, ph[b]);
        ph[b] ^= 1;
        const uint32_t cb = sb + b * ASTAGE_B;
        const uint32_t uKH = cb, uKL = cb + 8192, uVH = cb + 16384, uVL = cb + 24576;

        float sacc[8][4];
#pragma unroll
        for (int t = 0; t < 8; t++)
#pragma unroll
            for (int cc = 0; cc < 4; cc++) sacc[t][cc] = 0.f;
#pragma unroll
        for (int kk = 0; kk < 4; kk++) {
#pragma unroll
            for (int np = 0; np < 4; np++) {
                int r = np * 16 + brow_in;
                uint32_t off = r * 128 + (((2 * kk + bslot_in) ^ (r & 7)) * 16);
                uint32_t bfr[4];
                LDSM_X4(bfr[0], bfr[1], bfr[2], bfr[3], uKH + off);
                MMA_BF16(sacc[2 * np],     qh[kk], bfr[0], bfr[1]);
                MMA_BF16(sacc[2 * np + 1], qh[kk], bfr[2], bfr[3]);
                MMA_BF16(sacc[2 * np],     ql[kk], bfr[0], bfr[1]);
                MMA_BF16(sacc[2 * np + 1], ql[kk], bfr[2], bfr[3]);
                LDSM_X4(bfr[0], bfr[1], bfr[2], bfr[3], uKL + off);
                MMA_BF16(sacc[2 * np],     qh[kk], bfr[0], bfr[1]);
                MMA_BF16(sacc[2 * np + 1], qh[kk], bfr[2], bfr[3]);
            }
        }
        float rmax0 = NEG_INF, rmax1 = NEG_INF;
#pragma unroll
        for (int t = 0; t < 8; t++) {
#pragma unroll
            for (int cc = 0; cc < 4; cc++) {
                int row = r0g + ((cc >> 1) ? 8 : 0);
                int col = kb * 64 + t * 8 + 2 * quad + (cc & 1);
                int delta = row - col;
                bool valid = (delta >= 0) && ((delta <= 255) || ((delta & 63) == 0));
                float s = valid ? sacc[t][cc] : NEG_INF;
                sacc[t][cc] = s;
                if (cc < 2) rmax0 = fmaxf(rmax0, s);
                else        rmax1 = fmaxf(rmax1, s);
            }
        }
        rmax0 = fmaxf(rmax0, __shfl_xor_sync(0xFFFFFFFFu, rmax0, 1));
        rmax0 = fmaxf(rmax0, __shfl_xor_sync(0xFFFFFFFFu, rmax0, 2));
        rmax1 = fmaxf(rmax1, __shfl_xor_sync(0xFFFFFFFFu, rmax1, 1));
        rmax1 = fmaxf(rmax1, __shfl_xor_sync(0xFFFFFFFFu, rmax1, 2));
        float mn0 = fmaxf(m0, rmax0), mn1 = fmaxf(m1, rmax1);
        float c0 = __expf(m0 - mn0), c1 = __expf(m1 - mn1);
        float sum0 = 0.f, sum1 = 0.f;
#pragma unroll
        for (int t = 0; t < 8; t++) {
#pragma unroll
            for (int cc = 0; cc < 4; cc++) {
                float p = __expf(sacc[t][cc] - ((cc < 2) ? mn0 : mn1));
                sacc[t][cc] = p;
                if (cc < 2) sum0 += p; else sum1 += p;
            }
        }
        sum0 += __shfl_xor_sync(0xFFFFFFFFu, sum0, 1);
        sum0 += __shfl_xor_sync(0xFFFFFFFFu, sum0, 2);
        sum1 += __shfl_xor_sync(0xFFFFFFFFu, sum1, 1);
        sum1 += __shfl_xor_sync(0xFFFFFFFFu, sum1, 2);
        l0 = l0 * c0 + sum0;
        l1 = l1 * c1 + sum1;
#pragma unroll
        for (int t = 0; t < 8; t++) {
            oacc[t][0] *= c0; oacc[t][1] *= c0;
            oacc[t][2] *= c1; oacc[t][3] *= c1;
        }
        m0 = mn0; m1 = mn1;

#pragma unroll
        for (int j = 0; j < 4; j++) {
            uint32_t pfh[4], pfl[4];
            split_pack2(sacc[2 * j][0],     sacc[2 * j][1],     pfh[0], pfl[0]);
            split_pack2(sacc[2 * j][2],     sacc[2 * j][3],     pfh[1], pfl[1]);
            split_pack2(sacc[2 * j + 1][0], sacc[2 * j + 1][1], pfh[2], pfl[2]);
            split_pack2(sacc[2 * j + 1][2], sacc[2 * j + 1][3], pfh[3], pfl[3]);
#pragma unroll
            for (int np = 0; np < 4; np++) {
                int r = j * 16 + v_row_in;
                uint32_t off = r * 128 + (((2 * np + v_sel) ^ (r & 7)) * 16);
                uint32_t vh[4], vl[4];
                LDSM_X4_T(vh[0], vh[1], vh[2], vh[3], uVH + off);
                LDSM_X4_T(vl[0], vl[1], vl[2], vl[3], uVL + off);
                MMA_BF16(oacc[2 * np],     pfh, vh[0], vh[1]);
                MMA_BF16(oacc[2 * np],     pfl, vh[0], vh[1]);
                MMA_BF16(oacc[2 * np],     pfh, vl[0], vl[1]);
                MMA_BF16(oacc[2 * np + 1], pfh, vh[2], vh[3]);
                MMA_BF16(oacc[2 * np + 1], pfl, vh[2], vh[3]);
                MMA_BF16(oacc[2 * np + 1], pfh, vl[2], vl[3]);
            }
        }
        __syncthreads();
        if (i + 2 < nblk)
            issue_attn_stage(h, kb + 2, sb + b * ASTAGE_B, mb + 8 * b, tid);
    }

    // ---- merge with far partials, normalize, write PACKED tf32 O ----
    float fm0 = g_fm[r0g * NH + h];
    float fl0 = g_fl[r0g * NH + h];
    float fm1 = g_fm[(r0g + 8) * NH + h];
    float fl1 = g_fl[(r0g + 8) * NH + h];
    float mn0 = fmaxf(m0, fm0), mn1 = fmaxf(m1, fm1);
    float a0 = __expf(m0 - mn0), b0 = __expf(fm0 - mn0);
    float a1 = __expf(m1 - mn1), b1 = __expf(fm1 - mn1);
    float inv0 = 1.f / (a0 * l0 + b0 * fl0);
    float inv1 = 1.f / (a1 * l1 + b1 * fl1);
#pragma unroll
    for (int t = 0; t < 8; t++) {
        int col = h * HD + t * 8 + 2 * quad;
        float2 f0 = *(const float2*)(g_FO + (size_t)r0g * CDIM + col);
        float2 f1 = *(const float2*)(g_FO + (size_t)(r0g + 8) * CDIM + col);
        float o00 = (a0 * oacc[t][0] + b0 * f0.x) * inv0;
        float o01 = (a0 * oacc[t][1] + b0 * f0.y) * inv0;
        float o10 = (a1 * oacc[t][2] + b1 * f1.x) * inv1;
        float o11 = (a1 * oacc[t][3] + b1 * f1.y) * inv1;
        uint32_t t0, t1;
        CVT_TF32(t0, o00); CVT_TF32(t1, o01);
        *(uint2*)((char*)g_ot + packed_off32(r0g, col)) = make_uint2(t0, t1);
        CVT_TF32(t0, o10); CVT_TF32(t1, o11);
        *(uint2*)((char*)g_ot + packed_off32(r0g + 8, col)) = make_uint2(t0, t1);
    }
}

// ---------------- launch ----------------
extern "C" void kernel_launch(void* const* d_in, const int* in_sizes, int n_in,
                              void* d_out, int out_size)
{
    const float* x  = (const float*)d_in[0];
    const float* Wq = (const float*)d_in[1];
    const float* Wk = (const float*)d_in[2];
    const float* Wv = (const float*)d_in[3];
    const float* Wo = (const float*)d_in[4];
    float* out = (float*)d_out;

    cudaFuncSetAttribute(qkv_gemm,    cudaFuncAttributeMaxDynamicSharedMemorySize, SMEM_GEMM);
    cudaFuncSetAttribute(oproj_gemm,  cudaFuncAttributeMaxDynamicSharedMemorySize, SMEM_GEMM);
    cudaFuncSetAttribute(attn_kernel, cudaFuncAttributeMaxDynamicSharedMemorySize, SMEM_ATTN);

    pack_tf32_all<<<4096 + 4 * 1024, 256>>>(x, Wq, Wk, Wv, Wo);

    qkv_gemm<<<dim3(CDIM / 128, Tseq / 128, 3), 256, SMEM_GEMM>>>();

    kv_convert<<<1024, 128>>>();
    far_attn_kernel<<<dim3(64, NH), 128>>>();
    attn_kernel<<<dim3(Tseq / 64, NH), 128, SMEM_ATTN>>>();

    oproj_gemm<<<dim3(CDIM / 128, Tseq / 128), 256, SMEM_GEMM>>>(out);
}

// round 16
// speedup vs baseline: 1.1937x; 1.1937x over previous
#include <cuda_runtime.h>
#include <cuda_bf16.h>
#include <cstdint>
#include <cstddef>

using bf16 = __nv_bfloat16;

#define Tseq 4096
#define CDIM 1024
#define NH   16
#define HD   64
#define WSZ  (CDIM * CDIM)
#define NEG_INF (-1e30f)

// ---------------- scratch (device globals: no allocation allowed) ----------
__device__ float g_Q[Tseq * CDIM];
__device__ float g_K[Tseq * CDIM];
__device__ float g_V[Tseq * CDIM];
__device__ float g_FO[Tseq * CDIM];
__device__ float g_fm[Tseq * NH];
__device__ float g_fl[Tseq * NH];
// packed tile-blocked, pre-swizzled tf32 operands (GEMM):
// block (rtile, ks) at ((rtile*32 + ks) << 14); inside: row rr x chunk s:
// rr*128 + ((s ^ (rr&7)) << 4)
__device__ uint32_t g_xt[Tseq * CDIM];
__device__ uint32_t g_ot[Tseq * CDIM];
__device__ uint32_t g_wt[4 * WSZ];
// packed per-(head, kblock) 8KB pre-swizzled bf16 K/V tiles (attention)
__device__ bf16  g_kh[Tseq * CDIM];
__device__ bf16  g_kl[Tseq * CDIM];
__device__ bf16  g_vh[Tseq * CDIM];
__device__ bf16  g_vl[Tseq * CDIM];

// ---------------- helpers ----------------
__device__ __forceinline__ uint32_t smem_u32(const void* p) {
    uint32_t a;
    asm("{ .reg .u64 t; cvta.to.shared.u64 t, %1; cvt.u32.u64 %0, t; }" : "=r"(a) : "l"(p));
    return a;
}
__device__ __forceinline__ uint32_t lds32(uint32_t addr) {
    uint32_t v;
    asm volatile("ld.shared.b32 %0, [%1];" : "=r"(v) : "r"(addr));
    return v;
}

#define LDSM_X4(r0, r1, r2, r3, addr) \
    asm volatile("ldmatrix.sync.aligned.m8n8.x4.shared.b16 {%0,%1,%2,%3}, [%4];" \
                 : "=r"(r0), "=r"(r1), "=r"(r2), "=r"(r3) : "r"(addr))

#define LDSM_X4_T(r0, r1, r2, r3, addr) \
    asm volatile("ldmatrix.sync.aligned.m8n8.x4.trans.shared.b16 {%0,%1,%2,%3}, [%4];" \
                 : "=r"(r0), "=r"(r1), "=r"(r2), "=r"(r3) : "r"(addr))

#define MMA_BF16(c, a, b0, b1) \
    asm volatile("mma.sync.aligned.m16n8k16.row.col.f32.bf16.bf16.f32 " \
                 "{%0,%1,%2,%3}, {%4,%5,%6,%7}, {%8,%9}, {%0,%1,%2,%3};" \
                 : "+f"((c)[0]), "+f"((c)[1]), "+f"((c)[2]), "+f"((c)[3]) \
                 : "r"((a)[0]), "r"((a)[1]), "r"((a)[2]), "r"((a)[3]), "r"(b0), "r"(b1))

#define MMA_TF32(c, a, b0, b1) \
    asm volatile("mma.sync.aligned.m16n8k8.row.col.f32.tf32.tf32.f32 " \
                 "{%0,%1,%2,%3}, {%4,%5,%6,%7}, {%8,%9}, {%0,%1,%2,%3};" \
                 : "+f"((c)[0]), "+f"((c)[1]), "+f"((c)[2]), "+f"((c)[3]) \
                 : "r"((a)[0]), "r"((a)[1]), "r"((a)[2]), "r"((a)[3]), "r"(b0), "r"(b1))

#define PACK_BF16X2(d, hi, lo) \
    asm("cvt.rn.bf16x2.f32 %0, %1, %2;" : "=r"(d) : "f"(hi), "f"(lo))

#define CVT_TF32(d, f) \
    asm("cvt.rna.tf32.f32 %0, %1;" : "=r"(d) : "f"(f))

#define MBAR_INIT(a, c) asm volatile("mbarrier.init.shared.b64 [%0], %1;" :: "r"((uint32_t)(a)), "r"((uint32_t)(c)) : "memory")
#define MBAR_EXPECT(a, bytes) \
    asm volatile("mbarrier.arrive.expect_tx.shared.b64 _, [%0], %1;" :: "r"((uint32_t)(a)), "r"((uint32_t)(bytes)) : "memory")
#define MBAR_WAIT(a, ph) do {                                                            \
    uint32_t _m = (uint32_t)(a), _p = (uint32_t)(ph), _d;                                \
    asm volatile("{\n\t.reg .pred p;\n\tmbarrier.try_wait.parity.acquire.cta.shared::cta.b64 p, [%1], %2;\n\tselp.b32 %0, 1, 0, p;\n\t}" \
                 : "=r"(_d) : "r"(_m), "r"(_p) : "memory");                              \
    if (!_d) {                                                                           \
        asm volatile("{\n\t.reg .pred P1;\n\tWL_%=:\n\tmbarrier.try_wait.parity.acquire.cta.shared::cta.b64 P1, [%0], %1, 0x989680;\n\t@P1 bra.uni WD_%=;\n\tbra.uni WL_%=;\n\tWD_%=:\n\t}" \
                     :: "r"(_m), "r"(_p) : "memory");                                    \
    }                                                                                    \
} while (0)

#define CP_BULK(dst, src, n, mbar) \
    asm volatile("cp.async.bulk.shared::cluster.global.mbarrier::complete_tx::bytes [%0], [%1], %2, [%3];" \
                 :: "r"((uint32_t)(dst)), "l"(src), "r"((uint32_t)(n)), "r"((uint32_t)(mbar)) : "memory")

#define FENCE_ASYNC()  asm volatile("fence.proxy.async.shared::cta;" ::: "memory")

__device__ __forceinline__ void split_pack2(float a, float b, uint32_t& h2, uint32_t& l2)
{
    PACK_BF16X2(h2, b, a);
    float ar = a - __bfloat162float(__float2bfloat16(a));
    float br = b - __bfloat162float(__float2bfloat16(b));
    PACK_BF16X2(l2, br, ar);
}

// ---------------- fp32 -> packed pre-swizzled tf32 (x + 4 weights) ---------
__global__ __launch_bounds__(256) void pack_tf32_all(const float* __restrict__ x,
                                                     const float* __restrict__ Wq,
                                                     const float* __restrict__ Wk,
                                                     const float* __restrict__ Wv,
                                                     const float* __restrict__ Wo)
{
    int blk = blockIdx.x;
    const float* src;
    uint32_t* dst;
    int i;
    if (blk < 4096) {
        src = x; dst = g_xt;
        i = blk * 256 + threadIdx.x;
    } else {
        int wsel = (blk - 4096) >> 10;
        int wblk = (blk - 4096) & 1023;
        src = (wsel == 0) ? Wq : (wsel == 1) ? Wk : (wsel == 2) ? Wv : Wo;
        dst = g_wt + (size_t)wsel * WSZ;
        i = wblk * 256 + threadIdx.x;
    }
    int r = i >> 8;
    int c16 = i & 255;
    const float* sp = src + (size_t)r * CDIM + c16 * 4;
    float4 v = *(const float4*)sp;
    uint32_t t[4];
    CVT_TF32(t[0], v.x); CVT_TF32(t[1], v.y);
    CVT_TF32(t[2], v.z); CVT_TF32(t[3], v.w);
    int rt = r >> 7, rr = r & 127;
    int ks = c16 >> 3, s = c16 & 7;
    size_t boff = ((size_t)(rt * 32 + ks) << 14) + rr * 128 + ((s ^ (rr & 7)) << 4);
    *(uint4*)((char*)dst + boff) = *(uint4*)t;
}

// ---------------- K/V fp32 -> packed per-(h,kb) 8KB bf16 hi/lo tiles -------
__global__ __launch_bounds__(128) void kv_convert()
{
    int b = blockIdx.x;
    int h = b >> 6, kb = b & 63;
#pragma unroll
    for (int it = 0; it < 4; it++) {
        int id = threadIdx.x + it * 128;
        int r = id >> 3, s = id & 7;
        size_t goff = ((size_t)b << 13) + r * 128 + ((s ^ (r & 7)) << 4);
        const float* kp = g_K + (size_t)(kb * 64 + r) * CDIM + h * HD + s * 8;
        const float* vp = g_V + (size_t)(kb * 64 + r) * CDIM + h * HD + s * 8;
        float4 k0 = *(const float4*)kp, k1 = *(const float4*)(kp + 4);
        float4 w0 = *(const float4*)vp, w1 = *(const float4*)(vp + 4);
        float ka[8] = {k0.x, k0.y, k0.z, k0.w, k1.x, k1.y, k1.z, k1.w};
        float va[8] = {w0.x, w0.y, w0.z, w0.w, w1.x, w1.y, w1.z, w1.w};
        bf16 khh[8], kll[8], vhh[8], vll[8];
#pragma unroll
        for (int k = 0; k < 8; k++) {
            khh[k] = __float2bfloat16(ka[k]);
            kll[k] = __float2bfloat16(ka[k] - __bfloat162float(khh[k]));
            vhh[k] = __float2bfloat16(va[k]);
            vll[k] = __float2bfloat16(va[k] - __bfloat162float(vhh[k]));
        }
        *(uint4*)((char*)g_kh + goff) = *(uint4*)khh;
        *(uint4*)((char*)g_kl + goff) = *(uint4*)kll;
        *(uint4*)((char*)g_vh + goff) = *(uint4*)vhh;
        *(uint4*)((char*)g_vl + goff) = *(uint4*)vll;
    }
}

// ---------------- tf32 single-pass GEMM: C[4096,1024] = A @ B^T ------------
// CTA tile 128x128, BK=32 floats. 256 threads = 8 warps (4M x 2N).
// 3-stage bulk pipeline, 2 CTAs/SM (96KB smem each, 4 warps/SMSP).
constexpr int BLK_B = 16384;
constexpr int STG_B = 2 * BLK_B;
constexpr int NSTAGE = 3;
constexpr int SMEM_GEMM = NSTAGE * STG_B + 64;   // 98368

__device__ __forceinline__ void issue_stage(const uint32_t* __restrict__ A,
                                            const uint32_t* __restrict__ B,
                                            int bmT, int bnT, int kt,
                                            uint32_t bufu, uint32_t mbar, int tid)
{
    if (tid == 0) MBAR_EXPECT(mbar, STG_B);
    if (tid < 2) {
        const uint32_t* base = tid ? B : A;
        int rT = tid ? bnT : bmT;
        size_t bl = ((size_t)(rT * 32 + kt)) << 14;
        CP_BULK(bufu + tid * BLK_B, (const char*)base + bl, BLK_B, mbar);
    }
}

__device__ __forceinline__ void gemm_body(const uint32_t* __restrict__ A,
                                          const uint32_t* __restrict__ B,
                                          float* __restrict__ C)
{
    extern __shared__ __align__(128) unsigned char dynsmem[];
    uint32_t sb = smem_u32(dynsmem);
    const uint32_t mb = sb + NSTAGE * STG_B;
    const int tid = threadIdx.x;
    const int lane = tid & 31;
    const int wid = tid >> 5;
    const int bmT = blockIdx.y;
    const int bnT = blockIdx.x;
    const int m0 = (wid & 3) * 32;
    const int n0 = (wid >> 2) * 64;
    const int la = lane & 3;
    const int g4 = lane >> 2;

    if (tid == 0) {
#pragma unroll
        for (int s = 0; s < NSTAGE; s++) MBAR_INIT(mb + 8 * s, 1);
    }
    FENCE_ASYNC();
    __syncthreads();

    float acc[2][8][4];
#pragma unroll
    for (int mt = 0; mt < 2; mt++)
#pragma unroll
        for (int nt = 0; nt < 8; nt++)
#pragma unroll
            for (int c = 0; c < 4; c++) acc[mt][nt][c] = 0.f;

#pragma unroll
    for (int kt = 0; kt < NSTAGE; kt++)
        issue_stage(A, B, bmT, bnT, kt, sb + kt * STG_B, mb + 8 * kt, tid);

    int ph[NSTAGE] = {0, 0, 0};
    int b = 0;

#pragma unroll 1
    for (int kt = 0; kt < 32; ++kt) {
        MBAR_WAIT(mb + 8 * b, ph[b]);
        ph[b] ^= 1;
        const uint32_t cbA = sb + b * STG_B;
        const uint32_t cbB = cbA + BLK_B;

#pragma unroll
        for (int ks8 = 0; ks8 < 4; ++ks8) {
            const int ch0 = 2 * ks8;
            uint32_t af[2][4];
#pragma unroll
            for (int mt = 0; mt < 2; mt++) {
                int r0 = m0 + mt * 16 + g4;
                int xr = (r0 & 7);
                uint32_t b0a = cbA + r0 * 128 + la * 4;
                uint32_t b8a = b0a + 8 * 128;
                af[mt][0] = lds32(b0a + ((ch0 ^ xr) << 4));
                af[mt][1] = lds32(b8a + ((ch0 ^ xr) << 4));
                af[mt][2] = lds32(b0a + (((ch0 + 1) ^ xr) << 4));
                af[mt][3] = lds32(b8a + (((ch0 + 1) ^ xr) << 4));
            }
#pragma unroll
            for (int np = 0; np < 8; np++) {
                int n = n0 + np * 8 + g4;
                int xn = (n & 7);
                uint32_t bb = cbB + n * 128 + la * 4;
                uint32_t b0 = lds32(bb + ((ch0 ^ xn) << 4));
                uint32_t b1 = lds32(bb + (((ch0 + 1) ^ xn) << 4));
                MMA_TF32(acc[0][np], af[0], b0, b1);
                MMA_TF32(acc[1][np], af[1], b0, b1);
            }
        }
        __syncthreads();
        if (kt + NSTAGE < 32)
            issue_stage(A, B, bmT, bnT, kt + NSTAGE, sb + b * STG_B, mb + 8 * b, tid);
        b = (b + 1 == NSTAGE) ? 0 : b + 1;
    }

    // epilogue
#pragma unroll
    for (int mt = 0; mt < 2; mt++) {
        int row = bmT * 128 + m0 + mt * 16 + g4;
#pragma unroll
        for (int nt = 0; nt < 8; nt++) {
            int col = bnT * 128 + n0 + nt * 8 + 2 * la;
            float* p = C + (size_t)row * CDIM + col;
            *(float2*)p = make_float2(acc[mt][nt][0], acc[mt][nt][1]);
            *(float2*)(p + 8 * CDIM) = make_float2(acc[mt][nt][2], acc[mt][nt][3]);
        }
    }
}

__global__ __launch_bounds__(256, 2) void qkv_gemm()
{
    int z = blockIdx.z;
    float* C = (z == 0) ? g_Q : (z == 1) ? g_K : g_V;
    gemm_body(g_xt, g_wt + (size_t)z * WSZ, C);
}

__global__ __launch_bounds__(256, 2) void oproj_gemm(float* __restrict__ out)
{
    gemm_body(g_ot, g_wt + 3 * (size_t)WSZ, out);
}

// ---------------- attention helpers (far kernel) ----------------
__device__ __forceinline__ void stage_hl_s(const float* __restrict__ g, int base,
                                           int stride, int h, bf16* sh, bf16* sl,
                                           int tid)
{
#pragma unroll
    for (int s = 0; s < 4; s++) {
        int sid = tid + s * 128;
        int r = sid >> 3, sl8 = sid & 7;
        const float* src = g + (size_t)(base + r * stride) * CDIM + h * HD + sl8 * 8;
        float4 v0 = *(const float4*)src;
        float4 v1 = *(const float4*)(src + 4);
        float a[8] = {v0.x, v0.y, v0.z, v0.w, v1.x, v1.y, v1.z, v1.w};
        bf16 hi[8], lo[8];
#pragma unroll
        for (int k = 0; k < 8; k++) {
            hi[k] = __float2bfloat16(a[k]);
            lo[k] = __float2bfloat16(a[k] - __bfloat162float(hi[k]));
        }
        uint32_t off = r * 128 + ((sl8 ^ (r & 7)) * 16);
        *(uint4*)((char*)sh + off) = *(uint4*)hi;
        *(uint4*)((char*)sl + off) = *(uint4*)lo;
    }
}

// ---------------- far strided attention over residue classes ----------------
__global__ __launch_bounds__(128) void far_attn_kernel()
{
    __shared__ __align__(128) bf16 sKH[4096];
    __shared__ __align__(128) bf16 sKL[4096];
    __shared__ __align__(128) bf16 sVH[4096];
    __shared__ __align__(128) bf16 sVL[4096];

    const int c  = blockIdx.x;
    const int h  = blockIdx.y;
    const int tid = threadIdx.x;
    const int lane = tid & 31;
    const int w = tid >> 5;
    const int row16 = lane >> 2;
    const int quad = lane & 3;
    const int mrow = w * 16 + row16;
    const int q0row = c + 64 * mrow;
    const int q1row = q0row + 512;

    float q0[16], q1[16];
    {
        const float* qp0 = g_Q + (size_t)q0row * CDIM + h * HD;
        const float* qp1 = g_Q + (size_t)q1row * CDIM + h * HD;
#pragma unroll
        for (int j = 0; j < 8; j++) {
            float2 a = *(const float2*)(qp0 + 8 * j + 2 * quad);
            float2 b = *(const float2*)(qp1 + 8 * j + 2 * quad);
            q0[2 * j] = a.x * 0.125f; q0[2 * j + 1] = a.y * 0.125f;
            q1[2 * j] = b.x * 0.125f; q1[2 * j + 1] = b.y * 0.125f;
        }
    }
    uint32_t qh[4][4], ql[4][4];
#pragma unroll
    for (int kk = 0; kk < 4; kk++) {
        split_pack2(q0[4 * kk],     q0[4 * kk + 1], qh[kk][0], ql[kk][0]);
        split_pack2(q1[4 * kk],     q1[4 * kk + 1], qh[kk][1], ql[kk][1]);
        split_pack2(q0[4 * kk + 2], q0[4 * kk + 3], qh[kk][2], ql[kk][2]);
        split_pack2(q1[4 * kk + 2], q1[4 * kk + 3], qh[kk][3], ql[kk][3]);
    }

    stage_hl_s(g_K, c, 64, h, sKH, sKL, tid);
    stage_hl_s(g_V, c, 64, h, sVH, sVL, tid);
    __syncthreads();

    const uint32_t uKH = smem_u32(sKH), uKL = smem_u32(sKL);
    const uint32_t uVH = smem_u32(sVH), uVL = smem_u32(sVL);
    const int bmat = lane >> 3;
    const int brow_in = ((bmat & 2) ? 8 : 0) + (lane & 7);
    const int bslot_in = bmat & 1;
    const int v_row_in = ((lane >> 3) & 1) * 8 + (lane & 7);
    const int v_sel = lane >> 4;

    float sacc[8][4];
#pragma unroll
    for (int t = 0; t < 8; t++)
#pragma unroll
        for (int cc = 0; cc < 4; cc++) sacc[t][cc] = 0.f;
#pragma unroll
    for (int kk = 0; kk < 4; kk++) {
#pragma unroll
        for (int np = 0; np < 4; np++) {
            int r = np * 16 + brow_in;
            uint32_t off = r * 128 + (((2 * kk + bslot_in) ^ (r & 7)) * 16);
            uint32_t b[4];
            LDSM_X4(b[0], b[1], b[2], b[3], uKH + off);
            MMA_BF16(sacc[2 * np],     qh[kk], b[0], b[1]);
            MMA_BF16(sacc[2 * np + 1], qh[kk], b[2], b[3]);
            MMA_BF16(sacc[2 * np],     ql[kk], b[0], b[1]);
            MMA_BF16(sacc[2 * np + 1], ql[kk], b[2], b[3]);
            LDSM_X4(b[0], b[1], b[2], b[3], uKL + off);
            MMA_BF16(sacc[2 * np],     qh[kk], b[0], b[1]);
            MMA_BF16(sacc[2 * np + 1], qh[kk], b[2], b[3]);
        }
    }

    float rmax0 = NEG_INF, rmax1 = NEG_INF;
#pragma unroll
    for (int t = 0; t < 8; t++) {
#pragma unroll
        for (int cc = 0; cc < 4; cc++) {
            int m = mrow + ((cc >> 1) ? 8 : 0);
            int j = t * 8 + 2 * quad + (cc & 1);
            float s = (m - j >= 5) ? sacc[t][cc] : NEG_INF;
            sacc[t][cc] = s;
            if (cc < 2) rmax0 = fmaxf(rmax0, s);
            else        rmax1 = fmaxf(rmax1, s);
        }
    }
    rmax0 = fmaxf(rmax0, __shfl_xor_sync(0xFFFFFFFFu, rmax0, 1));
    rmax0 = fmaxf(rmax0, __shfl_xor_sync(0xFFFFFFFFu, rmax0, 2));
    rmax1 = fmaxf(rmax1, __shfl_xor_sync(0xFFFFFFFFu, rmax1, 1));
    rmax1 = fmaxf(rmax1, __shfl_xor_sync(0xFFFFFFFFu, rmax1, 2));
    float base0 = (rmax0 > -1e29f) ? 1.f : 0.f;
    float base1 = (rmax1 > -1e29f) ? 1.f : 0.f;
    float sum0 = 0.f, sum1 = 0.f;
#pragma unroll
    for (int t = 0; t < 8; t++) {
#pragma unroll
        for (int cc = 0; cc < 4; cc++) {
            float bb = (cc < 2) ? base0 : base1;
            float mm = (cc < 2) ? rmax0 : rmax1;
            float p = bb * __expf(sacc[t][cc] - mm);
            sacc[t][cc] = p;
            if (cc < 2) sum0 += p; else sum1 += p;
        }
    }
    sum0 += __shfl_xor_sync(0xFFFFFFFFu, sum0, 1);
    sum0 += __shfl_xor_sync(0xFFFFFFFFu, sum0, 2);
    sum1 += __shfl_xor_sync(0xFFFFFFFFu, sum1, 1);
    sum1 += __shfl_xor_sync(0xFFFFFFFFu, sum1, 2);

    float oacc[8][4];
#pragma unroll
    for (int t = 0; t < 8; t++)
#pragma unroll
        for (int cc = 0; cc < 4; cc++) oacc[t][cc] = 0.f;
#pragma unroll
    for (int j = 0; j < 4; j++) {
        uint32_t pfh[4], pfl[4];
        split_pack2(sacc[2 * j][0],     sacc[2 * j][1],     pfh[0], pfl[0]);
        split_pack2(sacc[2 * j][2],     sacc[2 * j][3],     pfh[1], pfl[1]);
        split_pack2(sacc[2 * j + 1][0], sacc[2 * j + 1][1], pfh[2], pfl[2]);
        split_pack2(sacc[2 * j + 1][2], sacc[2 * j + 1][3], pfh[3], pfl[3]);
#pragma unroll
        for (int np = 0; np < 4; np++) {
            int r = j * 16 + v_row_in;
            uint32_t off = r * 128 + (((2 * np + v_sel) ^ (r & 7)) * 16);
            uint32_t vh[4], vl[4];
            LDSM_X4_T(vh[0], vh[1], vh[2], vh[3], uVH + off);
            LDSM_X4_T(vl[0], vl[1], vl[2], vl[3], uVL + off);
            MMA_BF16(oacc[2 * np],     pfh, vh[0], vh[1]);
            MMA_BF16(oacc[2 * np],     pfl, vh[0], vh[1]);
            MMA_BF16(oacc[2 * np],     pfh, vl[0], vl[1]);
            MMA_BF16(oacc[2 * np + 1], pfh, vh[2], vh[3]);
            MMA_BF16(oacc[2 * np + 1], pfl, vh[2], vh[3]);
            MMA_BF16(oacc[2 * np + 1], pfh, vl[2], vl[3]);
        }
    }

#pragma unroll
    for (int t = 0; t < 8; t++) {
        int col = h * HD + t * 8 + 2 * quad;
        *(float2*)(g_FO + (size_t)q0row * CDIM + col) = make_float2(oacc[t][0], oacc[t][1]);
        *(float2*)(g_FO + (size_t)q1row * CDIM + col) = make_float2(oacc[t][2], oacc[t][3]);
    }
    if (quad == 0) {
        g_fm[q0row * NH + h] = rmax0;
        g_fl[q0row * NH + h] = sum0;
        g_fm[q1row * NH + h] = rmax1;
        g_fl[q1row * NH + h] = sum1;
    }
}

// packed tf32 write address for O
__device__ __forceinline__ size_t packed_off32(int row, int col)
{
    int rt = row >> 7, rr = row & 127;
    int ks = col >> 5;
    int c32 = col & 31;
    int s = c32 >> 2, idx = c32 & 3;
    return ((size_t)(rt * 32 + ks) << 14) + rr * 128 + ((s ^ (rr & 7)) << 4) + idx * 4;
}

// ---------------- window attention: bulk-staged pipeline -------------------
constexpr int ASTAGE_B = 32768;
constexpr int SMEM_ATTN = 2 * ASTAGE_B + 64;

__device__ __forceinline__ void issue_attn_stage(int h, int kb, uint32_t bufu,
                                                 uint32_t mbar, int tid)
{
    if (tid == 0) MBAR_EXPECT(mbar, ASTAGE_B);
    if (tid < 4) {
        const bf16* base = (tid == 0) ? g_kh : (tid == 1) ? g_kl : (tid == 2) ? g_vh : g_vl;
        size_t bl = ((size_t)(h * 64 + kb)) << 13;
        CP_BULK(bufu + tid * 8192, (const char*)base + bl, 8192, mbar);
    }
}

__global__ __launch_bounds__(128) void attn_kernel()
{
    extern __shared__ __align__(128) unsigned char dynsmem[];
    uint32_t sb = smem_u32(dynsmem);
    const uint32_t mb = sb + 2 * ASTAGE_B;

    const int qb = blockIdx.x;
    const int h  = blockIdx.y;
    const int tid = threadIdx.x;
    const int lane = tid & 31;
    const int w = tid >> 5;
    const int row16 = lane >> 2;
    const int quad = lane & 3;
    const int r0g = qb * 64 + w * 16 + row16;

    if (tid == 0) { MBAR_INIT(mb, 1); MBAR_INIT(mb + 8, 1); }
    FENCE_ASYNC();
    __syncthreads();

    const int wstart = (qb >= 4) ? qb - 4 : 0;
    const int nblk = qb - wstart + 1;

    issue_attn_stage(h, wstart, sb, mb, tid);
    if (nblk > 1) issue_attn_stage(h, wstart + 1, sb + ASTAGE_B, mb + 8, tid);

    float q0[16], q1[16];
    {
        const float* qp0 = g_Q + (size_t)r0g * CDIM + h * HD;
#pragma unroll
        for (int j = 0; j < 8; j++) {
            float2 a = *(const float2*)(qp0 + 8 * j + 2 * quad);
            float2 b = *(const float2*)(qp0 + 8 * CDIM + 8 * j + 2 * quad);
            q0[2 * j] = a.x * 0.125f; q0[2 * j + 1] = a.y * 0.125f;
            q1[2 * j] = b.x * 0.125f; q1[2 * j + 1] = b.y * 0.125f;
        }
    }
    uint32_t qh[4][4], ql[4][4];
#pragma unroll
    for (int kk = 0; kk < 4; kk++) {
        split_pack2(q0[4 * kk],     q0[4 * kk + 1], qh[kk][0], ql[kk][0]);
        split_pack2(q1[4 * kk],     q1[4 * kk + 1], qh[kk][1], ql[kk][1]);
        split_pack2(q0[4 * kk + 2], q0[4 * kk + 3], qh[kk][2], ql[kk][2]);
        split_pack2(q1[4 * kk + 2], q1[4 * kk + 3], qh[kk][3], ql[kk][3]);
    }

    float oacc[8][4];
#pragma unroll
    for (int t = 0; t < 8; t++)
#pragma unroll
        for (int cc = 0; cc < 4; cc++) oacc[t][cc] = 0.f;
    float m0 = NEG_INF, m1 = NEG_INF, l0 = 0.f, l1 = 0.f;

    const int bmat = lane >> 3;
    const int brow_in = ((bmat & 2) ? 8 : 0) + (lane & 7);
    const int bslot_in = bmat & 1;
    const int v_row_in = ((lane >> 3) & 1) * 8 + (lane & 7);
    const int v_sel = lane >> 4;

    int ph[2] = {0, 0};

#pragma unroll 1
    for (int i = 0; i < nblk; ++i) {
        const int kb = wstart + i;
        const int b = i & 1;
        MBAR_WAIT(mb + 8 * b, ph[b]);
        ph[b] ^= 1;
        const uint32_t cb = sb + b * ASTAGE_B;
        const uint32_t uKH = cb, uKL = cb + 8192, uVH = cb + 16384, uVL = cb + 24576;

        float sacc[8][4];
#pragma unroll
        for (int t = 0; t < 8; t++)
#pragma unroll
            for (int cc = 0; cc < 4; cc++) sacc[t][cc] = 0.f;
#pragma unroll
        for (int kk = 0; kk < 4; kk++) {
#pragma unroll
            for (int np = 0; np < 4; np++) {
                int r = np * 16 + brow_in;
                uint32_t off = r * 128 + (((2 * kk + bslot_in) ^ (r & 7)) * 16);
                uint32_t bfr[4];
                LDSM_X4(bfr[0], bfr[1], bfr[2], bfr[3], uKH + off);
                MMA_BF16(sacc[2 * np],     qh[kk], bfr[0], bfr[1]);
                MMA_BF16(sacc[2 * np + 1], qh[kk], bfr[2], bfr[3]);
                MMA_BF16(sacc[2 * np],     ql[kk], bfr[0], bfr[1]);
                MMA_BF16(sacc[2 * np + 1], ql[kk], bfr[2], bfr[3]);
                LDSM_X4(bfr[0], bfr[1], bfr[2], bfr[3], uKL + off);
                MMA_BF16(sacc[2 * np],     qh[kk], bfr[0], bfr[1]);
                MMA_BF16(sacc[2 * np + 1], qh[kk], bfr[2], bfr[3]);
            }
        }
        float rmax0 = NEG_INF, rmax1 = NEG_INF;
#pragma unroll
        for (int t = 0; t < 8; t++) {
#pragma unroll
            for (int cc = 0; cc < 4; cc++) {
                int row = r0g + ((cc >> 1) ? 8 : 0);
                int col = kb * 64 + t * 8 + 2 * quad + (cc & 1);
                int delta = row - col;
                bool valid = (delta >= 0) && ((delta <= 255) || ((delta & 63) == 0));
                float s = valid ? sacc[t][cc] : NEG_INF;
                sacc[t][cc] = s;
                if (cc < 2) rmax0 = fmaxf(rmax0, s);
                else        rmax1 = fmaxf(rmax1, s);
            }
        }
        rmax0 = fmaxf(rmax0, __shfl_xor_sync(0xFFFFFFFFu, rmax0, 1));
        rmax0 = fmaxf(rmax0, __shfl_xor_sync(0xFFFFFFFFu, rmax0, 2));
        rmax1 = fmaxf(rmax1, __shfl_xor_sync(0xFFFFFFFFu, rmax1, 1));
        rmax1 = fmaxf(rmax1, __shfl_xor_sync(0xFFFFFFFFu, rmax1, 2));
        float mn0 = fmaxf(m0, rmax0), mn1 = fmaxf(m1, rmax1);
        float c0 = __expf(m0 - mn0), c1 = __expf(m1 - mn1);
        float sum0 = 0.f, sum1 = 0.f;
#pragma unroll
        for (int t = 0; t < 8; t++) {
#pragma unroll
            for (int cc = 0; cc < 4; cc++) {
                float p = __expf(sacc[t][cc] - ((cc < 2) ? mn0 : mn1));
                sacc[t][cc] = p;
                if (cc < 2) sum0 += p; else sum1 += p;
            }
        }
        sum0 += __shfl_xor_sync(0xFFFFFFFFu, sum0, 1);
        sum0 += __shfl_xor_sync(0xFFFFFFFFu, sum0, 2);
        sum1 += __shfl_xor_sync(0xFFFFFFFFu, sum1, 1);
        sum1 += __shfl_xor_sync(0xFFFFFFFFu, sum1, 2);
        l0 = l0 * c0 + sum0;
        l1 = l1 * c1 + sum1;
#pragma unroll
        for (int t = 0; t < 8; t++) {
            oacc[t][0] *= c0; oacc[t][1] *= c0;
            oacc[t][2] *= c1; oacc[t][3] *= c1;
        }
        m0 = mn0; m1 = mn1;

#pragma unroll
        for (int j = 0; j < 4; j++) {
            uint32_t pfh[4], pfl[4];
            split_pack2(sacc[2 * j][0],     sacc[2 * j][1],     pfh[0], pfl[0]);
            split_pack2(sacc[2 * j][2],     sacc[2 * j][3],     pfh[1], pfl[1]);
            split_pack2(sacc[2 * j + 1][0], sacc[2 * j + 1][1], pfh[2], pfl[2]);
            split_pack2(sacc[2 * j + 1][2], sacc[2 * j + 1][3], pfh[3], pfl[3]);
#pragma unroll
            for (int np = 0; np < 4; np++) {
                int r = j * 16 + v_row_in;
                uint32_t off = r * 128 + (((2 * np + v_sel) ^ (r & 7)) * 16);
                uint32_t vh[4], vl[4];
                LDSM_X4_T(vh[0], vh[1], vh[2], vh[3], uVH + off);
                LDSM_X4_T(vl[0], vl[1], vl[2], vl[3], uVL + off);
                MMA_BF16(oacc[2 * np],     pfh, vh[0], vh[1]);
                MMA_BF16(oacc[2 * np],     pfl, vh[0], vh[1]);
                MMA_BF16(oacc[2 * np],     pfh, vl[0], vl[1]);
                MMA_BF16(oacc[2 * np + 1], pfh, vh[2], vh[3]);
                MMA_BF16(oacc[2 * np + 1], pfl, vh[2], vh[3]);
                MMA_BF16(oacc[2 * np + 1], pfh, vl[2], vl[3]);
            }
        }
        __syncthreads();
        if (i + 2 < nblk)
            issue_attn_stage(h, kb + 2, sb + b * ASTAGE_B, mb + 8 * b, tid);
    }

    // ---- merge with far partials, normalize, write PACKED tf32 O ----
    float fm0 = g_fm[r0g * NH + h];
    float fl0 = g_fl[r0g * NH + h];
    float fm1 = g_fm[(r0g + 8) * NH + h];
    float fl1 = g_fl[(r0g + 8) * NH + h];
    float mn0 = fmaxf(m0, fm0), mn1 = fmaxf(m1, fm1);
    float a0 = __expf(m0 - mn0), b0 = __expf(fm0 - mn0);
    float a1 = __expf(m1 - mn1), b1 = __expf(fm1 - mn1);
    float inv0 = 1.f / (a0 * l0 + b0 * fl0);
    float inv1 = 1.f / (a1 * l1 + b1 * fl1);
#pragma unroll
    for (int t = 0; t < 8; t++) {
        int col = h * HD + t * 8 + 2 * quad;
        float2 f0 = *(const float2*)(g_FO + (size_t)r0g * CDIM + col);
        float2 f1 = *(const float2*)(g_FO + (size_t)(r0g + 8) * CDIM + col);
        float o00 = (a0 * oacc[t][0] + b0 * f0.x) * inv0;
        float o01 = (a0 * oacc[t][1] + b0 * f0.y) * inv0;
        float o10 = (a1 * oacc[t][2] + b1 * f1.x) * inv1;
        float o11 = (a1 * oacc[t][3] + b1 * f1.y) * inv1;
        uint32_t t0, t1;
        CVT_TF32(t0, o00); CVT_TF32(t1, o01);
        *(uint2*)((char*)g_ot + packed_off32(r0g, col)) = make_uint2(t0, t1);
        CVT_TF32(t0, o10); CVT_TF32(t1, o11);
        *(uint2*)((char*)g_ot + packed_off32(r0g + 8, col)) = make_uint2(t0, t1);
    }
}

// ---------------- launch ----------------
extern "C" void kernel_launch(void* const* d_in, const int* in_sizes, int n_in,
                              void* d_out, int out_size)
{
    const float* x  = (const float*)d_in[0];
    const float* Wq = (const float*)d_in[1];
    const float* Wk = (const float*)d_in[2];
    const float* Wv = (const float*)d_in[3];
    const float* Wo = (const float*)d_in[4];
    float* out = (float*)d_out;

    cudaFuncSetAttribute(qkv_gemm,    cudaFuncAttributeMaxDynamicSharedMemorySize, SMEM_GEMM);
    cudaFuncSetAttribute(oproj_gemm,  cudaFuncAttributeMaxDynamicSharedMemorySize, SMEM_GEMM);
    cudaFuncSetAttribute(attn_kernel, cudaFuncAttributeMaxDynamicSharedMemorySize, SMEM_ATTN);

    pack_tf32_all<<<4096 + 4 * 1024, 256>>>(x, Wq, Wk, Wv, Wo);

    qkv_gemm<<<dim3(CDIM / 128, Tseq / 128, 3), 256, SMEM_GEMM>>>();

    kv_convert<<<1024, 128>>>();
    far_attn_kernel<<<dim3(64, NH), 128>>>();
    attn_kernel<<<dim3(Tseq / 64, NH), 128, SMEM_ATTN>>>();

    oproj_gemm<<<dim3(CDIM / 128, Tseq / 128), 256, SMEM_GEMM>>>(out);
}

// round 17
// speedup vs baseline: 1.2122x; 1.0155x over previous
#include <cuda_runtime.h>
#include <cuda_bf16.h>
#include <cstdint>
#include <cstddef>

using bf16 = __nv_bfloat16;

#define Tseq 4096
#define CDIM 1024
#define NH   16
#define HD   64
#define WSZ  (CDIM * CDIM)
#define NEG_INF (-1e30f)

// ---------------- scratch (device globals: no allocation allowed) ----------
__device__ float g_Q[Tseq * CDIM];
__device__ float g_FO[Tseq * CDIM];
__device__ float g_fm[Tseq * NH];
__device__ float g_fl[Tseq * NH];
// packed tile-blocked, pre-swizzled tf32 operands (GEMM):
// block (rtile, ks) at ((rtile*32 + ks) << 14); inside: row rr x chunk s:
// rr*128 + ((s ^ (rr&7)) << 4)
__device__ uint32_t g_xt[Tseq * CDIM];
__device__ uint32_t g_ot[Tseq * CDIM];
__device__ uint32_t g_wt[4 * WSZ];
// packed per-(head, kblock) 8KB pre-swizzled bf16 K/V tiles (attention):
// tile (h, kb) at ((h*64 + kb) << 13); inside: row r (token&63) x chunk s:
// r*128 + ((s ^ (r&7)) << 4), elem (d&7)*2 within chunk
__device__ bf16  g_kh[Tseq * CDIM];
__device__ bf16  g_kl[Tseq * CDIM];
__device__ bf16  g_vh[Tseq * CDIM];
__device__ bf16  g_vl[Tseq * CDIM];

// ---------------- helpers ----------------
__device__ __forceinline__ uint32_t smem_u32(const void* p) {
    uint32_t a;
    asm("{ .reg .u64 t; cvta.to.shared.u64 t, %1; cvt.u32.u64 %0, t; }" : "=r"(a) : "l"(p));
    return a;
}
__device__ __forceinline__ uint32_t lds32(uint32_t addr) {
    uint32_t v;
    asm volatile("ld.shared.b32 %0, [%1];" : "=r"(v) : "r"(addr));
    return v;
}

#define LDSM_X4(r0, r1, r2, r3, addr) \
    asm volatile("ldmatrix.sync.aligned.m8n8.x4.shared.b16 {%0,%1,%2,%3}, [%4];" \
                 : "=r"(r0), "=r"(r1), "=r"(r2), "=r"(r3) : "r"(addr))

#define LDSM_X4_T(r0, r1, r2, r3, addr) \
    asm volatile("ldmatrix.sync.aligned.m8n8.x4.trans.shared.b16 {%0,%1,%2,%3}, [%4];" \
                 : "=r"(r0), "=r"(r1), "=r"(r2), "=r"(r3) : "r"(addr))

#define MMA_BF16(c, a, b0, b1) \
    asm volatile("mma.sync.aligned.m16n8k16.row.col.f32.bf16.bf16.f32 " \
                 "{%0,%1,%2,%3}, {%4,%5,%6,%7}, {%8,%9}, {%0,%1,%2,%3};" \
                 : "+f"((c)[0]), "+f"((c)[1]), "+f"((c)[2]), "+f"((c)[3]) \
                 : "r"((a)[0]), "r"((a)[1]), "r"((a)[2]), "r"((a)[3]), "r"(b0), "r"(b1))

#define MMA_TF32(c, a, b0, b1) \
    asm volatile("mma.sync.aligned.m16n8k8.row.col.f32.tf32.tf32.f32 " \
                 "{%0,%1,%2,%3}, {%4,%5,%6,%7}, {%8,%9}, {%0,%1,%2,%3};" \
                 : "+f"((c)[0]), "+f"((c)[1]), "+f"((c)[2]), "+f"((c)[3]) \
                 : "r"((a)[0]), "r"((a)[1]), "r"((a)[2]), "r"((a)[3]), "r"(b0), "r"(b1))

#define PACK_BF16X2(d, hi, lo) \
    asm("cvt.rn.bf16x2.f32 %0, %1, %2;" : "=r"(d) : "f"(hi), "f"(lo))

#define CVT_TF32(d, f) \
    asm("cvt.rna.tf32.f32 %0, %1;" : "=r"(d) : "f"(f))

#define MBAR_INIT(a, c) asm volatile("mbarrier.init.shared.b64 [%0], %1;" :: "r"((uint32_t)(a)), "r"((uint32_t)(c)) : "memory")
#define MBAR_EXPECT(a, bytes) \
    asm volatile("mbarrier.arrive.expect_tx.shared.b64 _, [%0], %1;" :: "r"((uint32_t)(a)), "r"((uint32_t)(bytes)) : "memory")
#define MBAR_WAIT(a, ph) do {                                                            \
    uint32_t _m = (uint32_t)(a), _p = (uint32_t)(ph), _d;                                \
    asm volatile("{\n\t.reg .pred p;\n\tmbarrier.try_wait.parity.acquire.cta.shared::cta.b64 p, [%1], %2;\n\tselp.b32 %0, 1, 0, p;\n\t}" \
                 : "=r"(_d) : "r"(_m), "r"(_p) : "memory");                              \
    if (!_d) {                                                                           \
        asm volatile("{\n\t.reg .pred P1;\n\tWL_%=:\n\tmbarrier.try_wait.parity.acquire.cta.shared::cta.b64 P1, [%0], %1, 0x989680;\n\t@P1 bra.uni WD_%=;\n\tbra.uni WL_%=;\n\tWD_%=:\n\t}" \
                     :: "r"(_m), "r"(_p) : "memory");                                    \
    }                                                                                    \
} while (0)

#define CP_BULK(dst, src, n, mbar) \
    asm volatile("cp.async.bulk.shared::cluster.global.mbarrier::complete_tx::bytes [%0], [%1], %2, [%3];" \
                 :: "r"((uint32_t)(dst)), "l"(src), "r"((uint32_t)(n)), "r"((uint32_t)(mbar)) : "memory")

#define FENCE_ASYNC()  asm volatile("fence.proxy.async.shared::cta;" ::: "memory")

__device__ __forceinline__ void split_pack2(float a, float b, uint32_t& h2, uint32_t& l2)
{
    PACK_BF16X2(h2, b, a);
    float ar = a - __bfloat162float(__float2bfloat16(a));
    float br = b - __bfloat162float(__float2bfloat16(b));
    PACK_BF16X2(l2, br, ar);
}

// ---------------- fp32 -> packed pre-swizzled tf32 (x + 4 weights) ---------
__global__ __launch_bounds__(256) void pack_tf32_all(const float* __restrict__ x,
                                                     const float* __restrict__ Wq,
                                                     const float* __restrict__ Wk,
                                                     const float* __restrict__ Wv,
                                                     const float* __restrict__ Wo)
{
    int blk = blockIdx.x;
    const float* src;
    uint32_t* dst;
    int i;
    if (blk < 4096) {
        src = x; dst = g_xt;
        i = blk * 256 + threadIdx.x;
    } else {
        int wsel = (blk - 4096) >> 10;
        int wblk = (blk - 4096) & 1023;
        src = (wsel == 0) ? Wq : (wsel == 1) ? Wk : (wsel == 2) ? Wv : Wo;
        dst = g_wt + (size_t)wsel * WSZ;
        i = wblk * 256 + threadIdx.x;
    }
    int r = i >> 8;
    int c16 = i & 255;
    const float* sp = src + (size_t)r * CDIM + c16 * 4;
    float4 v = *(const float4*)sp;
    uint32_t t[4];
    CVT_TF32(t[0], v.x); CVT_TF32(t[1], v.y);
    CVT_TF32(t[2], v.z); CVT_TF32(t[3], v.w);
    int rt = r >> 7, rr = r & 127;
    int ks = c16 >> 3, s = c16 & 7;
    size_t boff = ((size_t)(rt * 32 + ks) << 14) + rr * 128 + ((s ^ (rr & 7)) << 4);
    *(uint4*)((char*)dst + boff) = *(uint4*)t;
}

// ---------------- tf32 single-pass GEMM: C[4096,1024] = A @ B^T ------------
// CTA tile 128x128, BK=32 floats. 256 threads = 8 warps (4M x 2N).
// 3-stage bulk pipeline, 2 CTAs/SM. mode 0: fp32 C out. mode 1: packed
// bf16 hi/lo K/V tile out (fused kv_convert).
constexpr int BLK_B = 16384;
constexpr int STG_B = 2 * BLK_B;
constexpr int NSTAGE = 3;
constexpr int SMEM_GEMM = NSTAGE * STG_B + 64;

__device__ __forceinline__ void issue_stage(const uint32_t* __restrict__ A,
                                            const uint32_t* __restrict__ B,
                                            int bmT, int bnT, int kt,
                                            uint32_t bufu, uint32_t mbar, int tid)
{
    if (tid == 0) MBAR_EXPECT(mbar, STG_B);
    if (tid < 2) {
        const uint32_t* base = tid ? B : A;
        int rT = tid ? bnT : bmT;
        size_t bl = ((size_t)(rT * 32 + kt)) << 14;
        CP_BULK(bufu + tid * BLK_B, (const char*)base + bl, BLK_B, mbar);
    }
}

__device__ __forceinline__ size_t kv_packed_off(int token, int col)
{
    int h = col >> 6, d = col & 63;
    int kb = token >> 6, r = token & 63;
    return ((size_t)(h * 64 + kb) << 13) + r * 128 + (((d >> 3) ^ (r & 7)) << 4) + (d & 7) * 2;
}

__device__ __forceinline__ void gemm_body(const uint32_t* __restrict__ A,
                                          const uint32_t* __restrict__ B,
                                          float* __restrict__ C,
                                          bf16* __restrict__ dh,
                                          bf16* __restrict__ dl,
                                          int mode)
{
    extern __shared__ __align__(128) unsigned char dynsmem[];
    uint32_t sb = smem_u32(dynsmem);
    const uint32_t mb = sb + NSTAGE * STG_B;
    const int tid = threadIdx.x;
    const int lane = tid & 31;
    const int wid = tid >> 5;
    const int bmT = blockIdx.y;
    const int bnT = blockIdx.x;
    const int m0 = (wid & 3) * 32;
    const int n0 = (wid >> 2) * 64;
    const int la = lane & 3;
    const int g4 = lane >> 2;

    if (tid == 0) {
#pragma unroll
        for (int s = 0; s < NSTAGE; s++) MBAR_INIT(mb + 8 * s, 1);
    }
    FENCE_ASYNC();
    __syncthreads();

    float acc[2][8][4];
#pragma unroll
    for (int mt = 0; mt < 2; mt++)
#pragma unroll
        for (int nt = 0; nt < 8; nt++)
#pragma unroll
            for (int c = 0; c < 4; c++) acc[mt][nt][c] = 0.f;

#pragma unroll
    for (int kt = 0; kt < NSTAGE; kt++)
        issue_stage(A, B, bmT, bnT, kt, sb + kt * STG_B, mb + 8 * kt, tid);

    int ph[NSTAGE] = {0, 0, 0};
    int b = 0;

#pragma unroll 1
    for (int kt = 0; kt < 32; ++kt) {
        MBAR_WAIT(mb + 8 * b, ph[b]);
        ph[b] ^= 1;
        const uint32_t cbA = sb + b * STG_B;
        const uint32_t cbB = cbA + BLK_B;

#pragma unroll
        for (int ks8 = 0; ks8 < 4; ++ks8) {
            const int ch0 = 2 * ks8;
            uint32_t af[2][4];
#pragma unroll
            for (int mt = 0; mt < 2; mt++) {
                int r0 = m0 + mt * 16 + g4;
                int xr = (r0 & 7);
                uint32_t b0a = cbA + r0 * 128 + la * 4;
                uint32_t b8a = b0a + 8 * 128;
                af[mt][0] = lds32(b0a + ((ch0 ^ xr) << 4));
                af[mt][1] = lds32(b8a + ((ch0 ^ xr) << 4));
                af[mt][2] = lds32(b0a + (((ch0 + 1) ^ xr) << 4));
                af[mt][3] = lds32(b8a + (((ch0 + 1) ^ xr) << 4));
            }
#pragma unroll
            for (int np = 0; np < 8; np++) {
                int n = n0 + np * 8 + g4;
                int xn = (n & 7);
                uint32_t bb = cbB + n * 128 + la * 4;
                uint32_t b0 = lds32(bb + ((ch0 ^ xn) << 4));
                uint32_t b1 = lds32(bb + (((ch0 + 1) ^ xn) << 4));
                MMA_TF32(acc[0][np], af[0], b0, b1);
                MMA_TF32(acc[1][np], af[1], b0, b1);
            }
        }
        __syncthreads();
        if (kt + NSTAGE < 32)
            issue_stage(A, B, bmT, bnT, kt + NSTAGE, sb + b * STG_B, mb + 8 * b, tid);
        b = (b + 1 == NSTAGE) ? 0 : b + 1;
    }

    // epilogue
    if (mode == 0) {
#pragma unroll
        for (int mt = 0; mt < 2; mt++) {
            int row = bmT * 128 + m0 + mt * 16 + g4;
#pragma unroll
            for (int nt = 0; nt < 8; nt++) {
                int col = bnT * 128 + n0 + nt * 8 + 2 * la;
                float* p = C + (size_t)row * CDIM + col;
                *(float2*)p = make_float2(acc[mt][nt][0], acc[mt][nt][1]);
                *(float2*)(p + 8 * CDIM) = make_float2(acc[mt][nt][2], acc[mt][nt][3]);
            }
        }
    } else {
        // packed bf16 hi/lo K/V tiles (fused kv_convert)
#pragma unroll
        for (int mt = 0; mt < 2; mt++) {
            int row = bmT * 128 + m0 + mt * 16 + g4;
#pragma unroll
            for (int nt = 0; nt < 8; nt++) {
                int col = bnT * 128 + n0 + nt * 8 + 2 * la;
                uint32_t h2, l2;
                size_t o0 = kv_packed_off(row, col);
                split_pack2(acc[mt][nt][0], acc[mt][nt][1], h2, l2);
                *(uint32_t*)((char*)dh + o0) = h2;
                *(uint32_t*)((char*)dl + o0) = l2;
                size_t o1 = kv_packed_off(row + 8, col);
                split_pack2(acc[mt][nt][2], acc[mt][nt][3], h2, l2);
                *(uint32_t*)((char*)dh + o1) = h2;
                *(uint32_t*)((char*)dl + o1) = l2;
            }
        }
    }
}

__global__ __launch_bounds__(256, 2) void qkv_gemm()
{
    int z = blockIdx.z;
    const uint32_t* B = g_wt + (size_t)z * WSZ;
    if (z == 0)      gemm_body(g_xt, B, g_Q, nullptr, nullptr, 0);
    else if (z == 1) gemm_body(g_xt, B, nullptr, g_kh, g_kl, 1);
    else             gemm_body(g_xt, B, nullptr, g_vh, g_vl, 1);
}

__global__ __launch_bounds__(256, 2) void oproj_gemm(float* __restrict__ out)
{
    gemm_body(g_ot, g_wt + 3 * (size_t)WSZ, out, nullptr, nullptr, 0);
}

// ---------------- far staging from packed bf16 tiles ----------------
// far CTA (c, h) needs row c of every tile (h, j), j=0..63, stored into a
// 64x64 smem tile at row j with local swizzle. Source byte pos p<<4 within
// the tile row holds chunk s = p ^ (c&7).
__device__ __forceinline__ void stage_far(const bf16* __restrict__ gsrc, int c,
                                          int h, bf16* sm, int tid)
{
    const int cx = c & 7;
#pragma unroll
    for (int it = 0; it < 4; it++) {
        int id = tid + it * 128;       // 0..511
        int j = id >> 3, p = id & 7;
        int s = p ^ cx;
        const char* src = (const char*)gsrc + (((size_t)(h * 64 + j)) << 13)
                          + c * 128 + (p << 4);
        uint4 v = *(const uint4*)src;
        *(uint4*)((char*)sm + j * 128 + ((s ^ (j & 7)) << 4)) = v;
    }
}

// ---------------- far strided attention over residue classes ----------------
__global__ __launch_bounds__(128) void far_attn_kernel()
{
    __shared__ __align__(128) bf16 sKH[4096];
    __shared__ __align__(128) bf16 sKL[4096];
    __shared__ __align__(128) bf16 sVH[4096];
    __shared__ __align__(128) bf16 sVL[4096];

    const int c  = blockIdx.x;
    const int h  = blockIdx.y;
    const int tid = threadIdx.x;
    const int lane = tid & 31;
    const int w = tid >> 5;
    const int row16 = lane >> 2;
    const int quad = lane & 3;
    const int mrow = w * 16 + row16;
    const int q0row = c + 64 * mrow;
    const int q1row = q0row + 512;

    float q0[16], q1[16];
    {
        const float* qp0 = g_Q + (size_t)q0row * CDIM + h * HD;
        const float* qp1 = g_Q + (size_t)q1row * CDIM + h * HD;
#pragma unroll
        for (int j = 0; j < 8; j++) {
            float2 a = *(const float2*)(qp0 + 8 * j + 2 * quad);
            float2 b = *(const float2*)(qp1 + 8 * j + 2 * quad);
            q0[2 * j] = a.x * 0.125f; q0[2 * j + 1] = a.y * 0.125f;
            q1[2 * j] = b.x * 0.125f; q1[2 * j + 1] = b.y * 0.125f;
        }
    }
    uint32_t qh[4][4], ql[4][4];
#pragma unroll
    for (int kk = 0; kk < 4; kk++) {
        split_pack2(q0[4 * kk],     q0[4 * kk + 1], qh[kk][0], ql[kk][0]);
        split_pack2(q1[4 * kk],     q1[4 * kk + 1], qh[kk][1], ql[kk][1]);
        split_pack2(q0[4 * kk + 2], q0[4 * kk + 3], qh[kk][2], ql[kk][2]);
        split_pack2(q1[4 * kk + 2], q1[4 * kk + 3], qh[kk][3], ql[kk][3]);
    }

    stage_far(g_kh, c, h, sKH, tid);
    stage_far(g_kl, c, h, sKL, tid);
    stage_far(g_vh, c, h, sVH, tid);
    stage_far(g_vl, c, h, sVL, tid);
    __syncthreads();

    const uint32_t uKH = smem_u32(sKH), uKL = smem_u32(sKL);
    const uint32_t uVH = smem_u32(sVH), uVL = smem_u32(sVL);
    const int bmat = lane >> 3;
    const int brow_in = ((bmat & 2) ? 8 : 0) + (lane & 7);
    const int bslot_in = bmat & 1;
    const int v_row_in = ((lane >> 3) & 1) * 8 + (lane & 7);
    const int v_sel = lane >> 4;

    float sacc[8][4];
#pragma unroll
    for (int t = 0; t < 8; t++)
#pragma unroll
        for (int cc = 0; cc < 4; cc++) sacc[t][cc] = 0.f;
#pragma unroll
    for (int kk = 0; kk < 4; kk++) {
#pragma unroll
        for (int np = 0; np < 4; np++) {
            int r = np * 16 + brow_in;
            uint32_t off = r * 128 + (((2 * kk + bslot_in) ^ (r & 7)) * 16);
            uint32_t b[4];
            LDSM_X4(b[0], b[1], b[2], b[3], uKH + off);
            MMA_BF16(sacc[2 * np],     qh[kk], b[0], b[1]);
            MMA_BF16(sacc[2 * np + 1], qh[kk], b[2], b[3]);
            MMA_BF16(sacc[2 * np],     ql[kk], b[0], b[1]);
            MMA_BF16(sacc[2 * np + 1], ql[kk], b[2], b[3]);
            LDSM_X4(b[0], b[1], b[2], b[3], uKL + off);
            MMA_BF16(sacc[2 * np],     qh[kk], b[0], b[1]);
            MMA_BF16(sacc[2 * np + 1], qh[kk], b[2], b[3]);
        }
    }

    float rmax0 = NEG_INF, rmax1 = NEG_INF;
#pragma unroll
    for (int t = 0; t < 8; t++) {
#pragma unroll
        for (int cc = 0; cc < 4; cc++) {
            int m = mrow + ((cc >> 1) ? 8 : 0);
            int j = t * 8 + 2 * quad + (cc & 1);
            float s = (m - j >= 5) ? sacc[t][cc] : NEG_INF;
            sacc[t][cc] = s;
            if (cc < 2) rmax0 = fmaxf(rmax0, s);
            else        rmax1 = fmaxf(rmax1, s);
        }
    }
    rmax0 = fmaxf(rmax0, __shfl_xor_sync(0xFFFFFFFFu, rmax0, 1));
    rmax0 = fmaxf(rmax0, __shfl_xor_sync(0xFFFFFFFFu, rmax0, 2));
    rmax1 = fmaxf(rmax1, __shfl_xor_sync(0xFFFFFFFFu, rmax1, 1));
    rmax1 = fmaxf(rmax1, __shfl_xor_sync(0xFFFFFFFFu, rmax1, 2));
    float base0 = (rmax0 > -1e29f) ? 1.f : 0.f;
    float base1 = (rmax1 > -1e29f) ? 1.f : 0.f;
    float sum0 = 0.f, sum1 = 0.f;
#pragma unroll
    for (int t = 0; t < 8; t++) {
#pragma unroll
        for (int cc = 0; cc < 4; cc++) {
            float bb = (cc < 2) ? base0 : base1;
            float mm = (cc < 2) ? rmax0 : rmax1;
            float p = bb * __expf(sacc[t][cc] - mm);
            sacc[t][cc] = p;
            if (cc < 2) sum0 += p; else sum1 += p;
        }
    }
    sum0 += __shfl_xor_sync(0xFFFFFFFFu, sum0, 1);
    sum0 += __shfl_xor_sync(0xFFFFFFFFu, sum0, 2);
    sum1 += __shfl_xor_sync(0xFFFFFFFFu, sum1, 1);
    sum1 += __shfl_xor_sync(0xFFFFFFFFu, sum1, 2);

    float oacc[8][4];
#pragma unroll
    for (int t = 0; t < 8; t++)
#pragma unroll
        for (int cc = 0; cc < 4; cc++) oacc[t][cc] = 0.f;
#pragma unroll
    for (int j = 0; j < 4; j++) {
        uint32_t pfh[4], pfl[4];
        split_pack2(sacc[2 * j][0],     sacc[2 * j][1],     pfh[0], pfl[0]);
        split_pack2(sacc[2 * j][2],     sacc[2 * j][3],     pfh[1], pfl[1]);
        split_pack2(sacc[2 * j + 1][0], sacc[2 * j + 1][1], pfh[2], pfl[2]);
        split_pack2(sacc[2 * j + 1][2], sacc[2 * j + 1][3], pfh[3], pfl[3]);
#pragma unroll
        for (int np = 0; np < 4; np++) {
            int r = j * 16 + v_row_in;
            uint32_t off = r * 128 + (((2 * np + v_sel) ^ (r & 7)) * 16);
            uint32_t vh[4], vl[4];
            LDSM_X4_T(vh[0], vh[1], vh[2], vh[3], uVH + off);
            LDSM_X4_T(vl[0], vl[1], vl[2], vl[3], uVL + off);
            MMA_BF16(oacc[2 * np],     pfh, vh[0], vh[1]);
            MMA_BF16(oacc[2 * np],     pfl, vh[0], vh[1]);
            MMA_BF16(oacc[2 * np],     pfh, vl[0], vl[1]);
            MMA_BF16(oacc[2 * np + 1], pfh, vh[2], vh[3]);
            MMA_BF16(oacc[2 * np + 1], pfl, vh[2], vh[3]);
            MMA_BF16(oacc[2 * np + 1], pfh, vl[2], vl[3]);
        }
    }

#pragma unroll
    for (int t = 0; t < 8; t++) {
        int col = h * HD + t * 8 + 2 * quad;
        *(float2*)(g_FO + (size_t)q0row * CDIM + col) = make_float2(oacc[t][0], oacc[t][1]);
        *(float2*)(g_FO + (size_t)q1row * CDIM + col) = make_float2(oacc[t][2], oacc[t][3]);
    }
    if (quad == 0) {
        g_fm[q0row * NH + h] = rmax0;
        g_fl[q0row * NH + h] = sum0;
        g_fm[q1row * NH + h] = rmax1;
        g_fl[q1row * NH + h] = sum1;
    }
}

// packed tf32 write address for O
__device__ __forceinline__ size_t packed_off32(int row, int col)
{
    int rt = row >> 7, rr = row & 127;
    int ks = col >> 5;
    int c32 = col & 31;
    int s = c32 >> 2, idx = c32 & 3;
    return ((size_t)(rt * 32 + ks) << 14) + rr * 128 + ((s ^ (rr & 7)) << 4) + idx * 4;
}

// ---------------- window attention: bulk-staged pipeline -------------------
constexpr int ASTAGE_B = 32768;
constexpr int SMEM_ATTN = 2 * ASTAGE_B + 64;

__device__ __forceinline__ void issue_attn_stage(int h, int kb, uint32_t bufu,
                                                 uint32_t mbar, int tid)
{
    if (tid == 0) MBAR_EXPECT(mbar, ASTAGE_B);
    if (tid < 4) {
        const bf16* base = (tid == 0) ? g_kh : (tid == 1) ? g_kl : (tid == 2) ? g_vh : g_vl;
        size_t bl = ((size_t)(h * 64 + kb)) << 13;
        CP_BULK(bufu + tid * 8192, (const char*)base + bl, 8192, mbar);
    }
}

__global__ __launch_bounds__(128) void attn_kernel()
{
    extern __shared__ __align__(128) unsigned char dynsmem[];
    uint32_t sb = smem_u32(dynsmem);
    const uint32_t mb = sb + 2 * ASTAGE_B;

    const int qb = blockIdx.x;
    const int h  = blockIdx.y;
    const int tid = threadIdx.x;
    const int lane = tid & 31;
    const int w = tid >> 5;
    const int row16 = lane >> 2;
    const int quad = lane & 3;
    const int r0g = qb * 64 + w * 16 + row16;

    if (tid == 0) { MBAR_INIT(mb, 1); MBAR_INIT(mb + 8, 1); }
    FENCE_ASYNC();
    __syncthreads();

    const int wstart = (qb >= 4) ? qb - 4 : 0;
    const int nblk = qb - wstart + 1;

    issue_attn_stage(h, wstart, sb, mb, tid);
    if (nblk > 1) issue_attn_stage(h, wstart + 1, sb + ASTAGE_B, mb + 8, tid);

    float q0[16], q1[16];
    {
        const float* qp0 = g_Q + (size_t)r0g * CDIM + h * HD;
#pragma unroll
        for (int j = 0; j < 8; j++) {
            float2 a = *(const float2*)(qp0 + 8 * j + 2 * quad);
            float2 b = *(const float2*)(qp0 + 8 * CDIM + 8 * j + 2 * quad);
            q0[2 * j] = a.x * 0.125f; q0[2 * j + 1] = a.y * 0.125f;
            q1[2 * j] = b.x * 0.125f; q1[2 * j + 1] = b.y * 0.125f;
        }
    }
    uint32_t qh[4][4], ql[4][4];
#pragma unroll
    for (int kk = 0; kk < 4; kk++) {
        split_pack2(q0[4 * kk],     q0[4 * kk + 1], qh[kk][0], ql[kk][0]);
        split_pack2(q1[4 * kk],     q1[4 * kk + 1], qh[kk][1], ql[kk][1]);
        split_pack2(q0[4 * kk + 2], q0[4 * kk + 3], qh[kk][2], ql[kk][2]);
        split_pack2(q1[4 * kk + 2], q1[4 * kk + 3], qh[kk][3], ql[kk][3]);
    }

    float oacc[8][4];
#pragma unroll
    for (int t = 0; t < 8; t++)
#pragma unroll
        for (int cc = 0; cc < 4; cc++) oacc[t][cc] = 0.f;
    float m0 = NEG_INF, m1 = NEG_INF, l0 = 0.f, l1 = 0.f;

    const int bmat = lane >> 3;
    const int brow_in = ((bmat & 2) ? 8 : 0) + (lane & 7);
    const int bslot_in = bmat & 1;
    const int v_row_in = ((lane >> 3) & 1) * 8 + (lane & 7);
    const int v_sel = lane >> 4;

    int ph[2] = {0, 0};

#pragma unroll 1
    for (int i = 0; i < nblk; ++i) {
        const int kb = wstart + i;
        const int b = i & 1;
        MBAR_WAIT(mb + 8 * b, ph[b]);
        ph[b] ^= 1;
        const uint32_t cb = sb + b * ASTAGE_B;
        const uint32_t uKH = cb, uKL = cb + 8192, uVH = cb + 16384, uVL = cb + 24576;

        float sacc[8][4];
#pragma unroll
        for (int t = 0; t < 8; t++)
#pragma unroll
            for (int cc = 0; cc < 4; cc++) sacc[t][cc] = 0.f;
#pragma unroll
        for (int kk = 0; kk < 4; kk++) {
#pragma unroll
            for (int np = 0; np < 4; np++) {
                int r = np * 16 + brow_in;
                uint32_t off = r * 128 + (((2 * kk + bslot_in) ^ (r & 7)) * 16);
                uint32_t bfr[4];
                LDSM_X4(bfr[0], bfr[1], bfr[2], bfr[3], uKH + off);
                MMA_BF16(sacc[2 * np],     qh[kk], bfr[0], bfr[1]);
                MMA_BF16(sacc[2 * np + 1], qh[kk], bfr[2], bfr[3]);
                MMA_BF16(sacc[2 * np],     ql[kk], bfr[0], bfr[1]);
                MMA_BF16(sacc[2 * np + 1], ql[kk], bfr[2], bfr[3]);
                LDSM_X4(bfr[0], bfr[1], bfr[2], bfr[3], uKL + off);
                MMA_BF16(sacc[2 * np],     qh[kk], bfr[0], bfr[1]);
                MMA_BF16(sacc[2 * np + 1], qh[kk], bfr[2], bfr[3]);
            }
        }
        float rmax0 = NEG_INF, rmax1 = NEG_INF;
#pragma unroll
        for (int t = 0; t < 8; t++) {
#pragma unroll
            for (int cc = 0; cc < 4; cc++) {
                int row = r0g + ((cc >> 1) ? 8 : 0);
                int col = kb * 64 + t * 8 + 2 * quad + (cc & 1);
                int delta = row - col;
                bool valid = (delta >= 0) && ((delta <= 255) || ((delta & 63) == 0));
                float s = valid ? sacc[t][cc] : NEG_INF;
                sacc[t][cc] = s;
                if (cc < 2) rmax0 = fmaxf(rmax0, s);
                else        rmax1 = fmaxf(rmax1, s);
            }
        }
        rmax0 = fmaxf(rmax0, __shfl_xor_sync(0xFFFFFFFFu, rmax0, 1));
        rmax0 = fmaxf(rmax0, __shfl_xor_sync(0xFFFFFFFFu, rmax0, 2));
        rmax1 = fmaxf(rmax1, __shfl_xor_sync(0xFFFFFFFFu, rmax1, 1));
        rmax1 = fmaxf(rmax1, __shfl_xor_sync(0xFFFFFFFFu, rmax1, 2));
        float mn0 = fmaxf(m0, rmax0), mn1 = fmaxf(m1, rmax1);
        float c0 = __expf(m0 - mn0), c1 = __expf(m1 - mn1);
        float sum0 = 0.f, sum1 = 0.f;
#pragma unroll
        for (int t = 0; t < 8; t++) {
#pragma unroll
            for (int cc = 0; cc < 4; cc++) {
                float p = __expf(sacc[t][cc] - ((cc < 2) ? mn0 : mn1));
                sacc[t][cc] = p;
                if (cc < 2) sum0 += p; else sum1 += p;
            }
        }
        sum0 += __shfl_xor_sync(0xFFFFFFFFu, sum0, 1);
        sum0 += __shfl_xor_sync(0xFFFFFFFFu, sum0, 2);
        sum1 += __shfl_xor_sync(0xFFFFFFFFu, sum1, 1);
        sum1 += __shfl_xor_sync(0xFFFFFFFFu, sum1, 2);
        l0 = l0 * c0 + sum0;
        l1 = l1 * c1 + sum1;
#pragma unroll
        for (int t = 0; t < 8; t++) {
            oacc[t][0] *= c0; oacc[t][1] *= c0;
            oacc[t][2] *= c1; oacc[t][3] *= c1;
        }
        m0 = mn0; m1 = mn1;

#pragma unroll
        for (int j = 0; j < 4; j++) {
            uint32_t pfh[4], pfl[4];
            split_pack2(sacc[2 * j][0],     sacc[2 * j][1],     pfh[0], pfl[0]);
            split_pack2(sacc[2 * j][2],     sacc[2 * j][3],     pfh[1], pfl[1]);
            split_pack2(sacc[2 * j + 1][0], sacc[2 * j + 1][1], pfh[2], pfl[2]);
            split_pack2(sacc[2 * j + 1][2], sacc[2 * j + 1][3], pfh[3], pfl[3]);
#pragma unroll
            for (int np = 0; np < 4; np++) {
                int r = j * 16 + v_row_in;
                uint32_t off = r * 128 + (((2 * np + v_sel) ^ (r & 7)) * 16);
                uint32_t vh[4], vl[4];
                LDSM_X4_T(vh[0], vh[1], vh[2], vh[3], uVH + off);
                LDSM_X4_T(vl[0], vl[1], vl[2], vl[3], uVL + off);
                MMA_BF16(oacc[2 * np],     pfh, vh[0], vh[1]);
                MMA_BF16(oacc[2 * np],     pfl, vh[0], vh[1]);
                MMA_BF16(oacc[2 * np],     pfh, vl[0], vl[1]);
                MMA_BF16(oacc[2 * np + 1], pfh, vh[2], vh[3]);
                MMA_BF16(oacc[2 * np + 1], pfl, vh[2], vh[3]);
                MMA_BF16(oacc[2 * np + 1], pfh, vl[2], vl[3]);
            }
        }
        __syncthreads();
        if (i + 2 < nblk)
            issue_attn_stage(h, kb + 2, sb + b * ASTAGE_B, mb + 8 * b, tid);
    }

    // ---- merge with far partials, normalize, write PACKED tf32 O ----
    float fm0 = g_fm[r0g * NH + h];
    float fl0 = g_fl[r0g * NH + h];
    float fm1 = g_fm[(r0g + 8) * NH + h];
    float fl1 = g_fl[(r0g + 8) * NH + h];
    float mn0 = fmaxf(m0, fm0), mn1 = fmaxf(m1, fm1);
    float a0 = __expf(m0 - mn0), b0 = __expf(fm0 - mn0);
    float a1 = __expf(m1 - mn1), b1 = __expf(fm1 - mn1);
    float inv0 = 1.f / (a0 * l0 + b0 * fl0);
    float inv1 = 1.f / (a1 * l1 + b1 * fl1);
#pragma unroll
    for (int t = 0; t < 8; t++) {
        int col = h * HD + t * 8 + 2 * quad;
        float2 f0 = *(const float2*)(g_FO + (size_t)r0g * CDIM + col);
        float2 f1 = *(const float2*)(g_FO + (size_t)(r0g + 8) * CDIM + col);
        float o00 = (a0 * oacc[t][0] + b0 * f0.x) * inv0;
        float o01 = (a0 * oacc[t][1] + b0 * f0.y) * inv0;
        float o10 = (a1 * oacc[t][2] + b1 * f1.x) * inv1;
        float o11 = (a1 * oacc[t][3] + b1 * f1.y) * inv1;
        uint32_t t0, t1;
        CVT_TF32(t0, o00); CVT_TF32(t1, o01);
        *(uint2*)((char*)g_ot + packed_off32(r0g, col)) = make_uint2(t0, t1);
        CVT_TF32(t0, o10); CVT_TF32(t1, o11);
        *(uint2*)((char*)g_ot + packed_off32(r0g + 8, col)) = make_uint2(t0, t1);
    }
}

// ---------------- launch ----------------
extern "C" void kernel_launch(void* const* d_in, const int* in_sizes, int n_in,
                              void* d_out, int out_size)
{
    const float* x  = (const float*)d_in[0];
    const float* Wq = (const float*)d_in[1];
    const float* Wk = (const float*)d_in[2];
    const float* Wv = (const float*)d_in[3];
    const float* Wo = (const float*)d_in[4];
    float* out = (float*)d_out;

    cudaFuncSetAttribute(qkv_gemm,    cudaFuncAttributeMaxDynamicSharedMemorySize, SMEM_GEMM);
    cudaFuncSetAttribute(oproj_gemm,  cudaFuncAttributeMaxDynamicSharedMemorySize, SMEM_GEMM);
    cudaFuncSetAttribute(attn_kernel, cudaFuncAttributeMaxDynamicSharedMemorySize, SMEM_ATTN);

    pack_tf32_all<<<4096 + 4 * 1024, 256>>>(x, Wq, Wk, Wv, Wo);

    qkv_gemm<<<dim3(CDIM / 128, Tseq / 128, 3), 256, SMEM_GEMM>>>();

    far_attn_kernel<<<dim3(64, NH), 128>>>();
    attn_kernel<<<dim3(Tseq / 64, NH), 128, SMEM_ATTN>>>();

    oproj_gemm<<<dim3(CDIM / 128, Tseq / 128), 256, SMEM_GEMM>>>(out);
}